// round 2
// baseline (speedup 1.0000x reference)
#include <cuda_runtime.h>
#include <math.h>

#define Bb 4
#define Tt 2048
#define Cc 1024
#define Hh 16
#define Dd 64

// Scratch (no cudaMalloc allowed): qkv = 100.7MB, att = 33.5MB
__device__ float g_qkv[Bb * Tt * 3 * Cc];
__device__ float g_att[Bb * Tt * Cc];

// ---------------------------------------------------------------------------
// Generic fp32 SGEMM: C[M,N] = A[M,K] @ B[K,N], all row-major.
// Block tile 128x128, K-tile 8, 256 threads, 8x8 micro-tile per thread.
// M, N, K assumed multiples of 128/8 (true here).
// ---------------------------------------------------------------------------
__global__ __launch_bounds__(256) void sgemm128(const float* __restrict__ A,
                                                const float* __restrict__ Bm,
                                                float* __restrict__ Cm,
                                                int N, int K) {
    __shared__ float As[8][128];   // transposed A tile: As[k][m]
    __shared__ float Bs[8][128];   // Bs[k][n]
    const int tid = threadIdx.x;
    const int tx = tid & 15;
    const int ty = tid >> 4;
    const int arow = tid >> 1;          // 0..127
    const int acol = (tid & 1) << 2;    // 0 or 4
    const int brow = tid >> 5;          // 0..7
    const int bcol = (tid & 31) << 2;   // 0..124

    const float* Ab = A + (size_t)blockIdx.y * 128 * K;
    const float* Bb2 = Bm + blockIdx.x * 128;
    float* Cb = Cm + (size_t)blockIdx.y * 128 * N + blockIdx.x * 128;

    float acc[8][8];
#pragma unroll
    for (int i = 0; i < 8; i++)
#pragma unroll
        for (int j = 0; j < 8; j++) acc[i][j] = 0.f;

    for (int k0 = 0; k0 < K; k0 += 8) {
        float4 av = *(const float4*)(Ab + (size_t)arow * K + k0 + acol);
        As[acol + 0][arow] = av.x;
        As[acol + 1][arow] = av.y;
        As[acol + 2][arow] = av.z;
        As[acol + 3][arow] = av.w;
        *(float4*)&Bs[brow][bcol] =
            *(const float4*)(Bb2 + (size_t)(k0 + brow) * N + bcol);
        __syncthreads();
#pragma unroll
        for (int kk = 0; kk < 8; kk++) {
            float4 a0 = *(const float4*)&As[kk][ty * 8];
            float4 a1 = *(const float4*)&As[kk][ty * 8 + 4];
            float4 b0 = *(const float4*)&Bs[kk][tx * 8];
            float4 b1 = *(const float4*)&Bs[kk][tx * 8 + 4];
            float ra[8] = {a0.x, a0.y, a0.z, a0.w, a1.x, a1.y, a1.z, a1.w};
            float rb[8] = {b0.x, b0.y, b0.z, b0.w, b1.x, b1.y, b1.z, b1.w};
#pragma unroll
            for (int i = 0; i < 8; i++)
#pragma unroll
                for (int j = 0; j < 8; j++)
                    acc[i][j] = fmaf(ra[i], rb[j], acc[i][j]);
        }
        __syncthreads();
    }
#pragma unroll
    for (int i = 0; i < 8; i++) {
        float* cp = Cb + (size_t)(ty * 8 + i) * N + tx * 8;
        *(float4*)cp = make_float4(acc[i][0], acc[i][1], acc[i][2], acc[i][3]);
        *(float4*)(cp + 4) = make_float4(acc[i][4], acc[i][5], acc[i][6], acc[i][7]);
    }
}

// ---------------------------------------------------------------------------
// RoPE in-place on q and k sections of g_qkv.
// One block per (b,t); 512 threads = 16 heads x 32 pairs.
// Trig computed in double (immune to fast-math sinf range-reduction error;
// args go up to 2047 rad).
// ---------------------------------------------------------------------------
__global__ __launch_bounds__(512) void rope_kernel(float* __restrict__ qkv) {
    __shared__ float sc[32], ss[32];
    const int bt = blockIdx.x;          // b*T + t
    const int t = bt & (Tt - 1);
    const int j = threadIdx.x;
    if (j < 32) {
        double invf = pow(10000.0, -(double)j / 32.0);
        double a = (double)t * invf;
        sc[j] = (float)cos(a);
        ss[j] = (float)sin(a);
    }
    __syncthreads();
    const int h = j >> 5;
    const int i = j & 31;
    const float c = sc[i], s = ss[i];
    float2* qp = (float2*)(qkv + (size_t)bt * 3072 + h * 64);
    float2 q = qp[i];
    qp[i] = make_float2(q.x * c - q.y * s, q.y * c + q.x * s);
    float2* kp = (float2*)(qkv + (size_t)bt * 3072 + 1024 + h * 64);
    float2 k = kp[i];
    kp[i] = make_float2(k.x * c - k.y * s, k.y * c + k.x * s);
}

// ---------------------------------------------------------------------------
// Causal flash attention, fp32. BM=BN=64, D=64, 256 threads (16x16),
// each thread computes a 4x4 micro-tile. Online softmax with width-16
// shuffle butterflies. Q pre-scaled by 1/sqrt(D)=0.125 (exact pow2).
// grid = (T/64, B*H). Dynamic smem: Qs+Ks+Vs [64][64] + Ps [64][68].
// ---------------------------------------------------------------------------
#define FLASH_SMEM ((3 * 64 * 64 + 64 * 68) * 4)

__global__ __launch_bounds__(256) void flash64(const float* __restrict__ qkv,
                                               float* __restrict__ att) {
    extern __shared__ float sm[];
    float(*Qs)[64] = (float(*)[64])sm;               // [d][m]
    float(*Ks)[64] = (float(*)[64])(sm + 64 * 64);   // [d][n]
    float(*Vs)[64] = (float(*)[64])(sm + 2 * 64 * 64); // [n][d]
    float(*Ps)[68] = (float(*)[68])(sm + 3 * 64 * 64); // [m][n], padded

    const int iq = blockIdx.x;
    const int bh = blockIdx.y;
    const int b = bh >> 4;
    const int h = bh & 15;
    const int tid = threadIdx.x;
    const int tx = tid & 15;
    const int ty = tid >> 4;

    const float* base = qkv + (size_t)b * Tt * 3072 + h * 64;

    // Load Q transposed (d-major loader -> conflict-free STS), pre-scaled.
    {
        const int r = tid & 63;
        const int c4base = tid >> 6;
        const float* qrow = base + (size_t)(iq * 64 + r) * 3072;
#pragma unroll
        for (int rep = 0; rep < 4; rep++) {
            int c4 = c4base + rep * 4;
            float4 v = *(const float4*)(qrow + c4 * 4);
            Qs[c4 * 4 + 0][r] = v.x * 0.125f;
            Qs[c4 * 4 + 1][r] = v.y * 0.125f;
            Qs[c4 * 4 + 2][r] = v.z * 0.125f;
            Qs[c4 * 4 + 3][r] = v.w * 0.125f;
        }
    }

    float o[4][4];
    float m_i[4], l_i[4];
#pragma unroll
    for (int i = 0; i < 4; i++) {
        m_i[i] = -1e30f;
        l_i[i] = 0.f;
#pragma unroll
        for (int j = 0; j < 4; j++) o[i][j] = 0.f;
    }

    for (int jt = 0; jt <= iq; jt++) {
        __syncthreads();  // prev GEMM2 done reading Vs/Ps before overwrite
        {
            const int r = tid & 63;
            const int c4base = tid >> 6;
            const float* krow = base + (size_t)(jt * 64 + r) * 3072 + 1024;
#pragma unroll
            for (int rep = 0; rep < 4; rep++) {
                int c4 = c4base + rep * 4;
                float4 kv = *(const float4*)(krow + c4 * 4);
                Ks[c4 * 4 + 0][r] = kv.x;
                Ks[c4 * 4 + 1][r] = kv.y;
                Ks[c4 * 4 + 2][r] = kv.z;
                Ks[c4 * 4 + 3][r] = kv.w;
            }
#pragma unroll
            for (int rep = 0; rep < 4; rep++) {
                int idx = tid + rep * 256;
                int rv = idx >> 4;
                int cv = (idx & 15) << 2;
                *(float4*)&Vs[rv][cv] =
                    *(const float4*)(base + (size_t)(jt * 64 + rv) * 3072 + 2048 + cv);
            }
        }
        __syncthreads();

        // S = Q @ K^T  (already scaled via Q)
        float s[4][4];
#pragma unroll
        for (int i = 0; i < 4; i++)
#pragma unroll
            for (int jj = 0; jj < 4; jj++) s[i][jj] = 0.f;

#pragma unroll 8
        for (int kk = 0; kk < 64; kk++) {
            float4 qa = *(const float4*)&Qs[kk][ty * 4];
            float4 kb = *(const float4*)&Ks[kk][tx * 4];
            float ra[4] = {qa.x, qa.y, qa.z, qa.w};
            float rb[4] = {kb.x, kb.y, kb.z, kb.w};
#pragma unroll
            for (int i = 0; i < 4; i++)
#pragma unroll
                for (int jj = 0; jj < 4; jj++)
                    s[i][jj] = fmaf(ra[i], rb[jj], s[i][jj]);
        }

        if (jt == iq) {  // diagonal tile: causal mask
#pragma unroll
            for (int i = 0; i < 4; i++)
#pragma unroll
                for (int jj = 0; jj < 4; jj++)
                    if (tx * 4 + jj > ty * 4 + i) s[i][jj] = -1e30f;
        }

        // Online softmax update (row groups = 16-lane shuffle segments)
#pragma unroll
        for (int i = 0; i < 4; i++) {
            float rmax = fmaxf(fmaxf(s[i][0], s[i][1]), fmaxf(s[i][2], s[i][3]));
#pragma unroll
            for (int off = 8; off >= 1; off >>= 1)
                rmax = fmaxf(rmax, __shfl_xor_sync(0xffffffffu, rmax, off, 16));
            float mnew = fmaxf(m_i[i], rmax);
            float al = __expf(m_i[i] - mnew);
            float rs = 0.f;
#pragma unroll
            for (int jj = 0; jj < 4; jj++) {
                s[i][jj] = __expf(s[i][jj] - mnew);
                rs += s[i][jj];
            }
#pragma unroll
            for (int off = 8; off >= 1; off >>= 1)
                rs += __shfl_xor_sync(0xffffffffu, rs, off, 16);
            l_i[i] = l_i[i] * al + rs;
            m_i[i] = mnew;
#pragma unroll
            for (int jj = 0; jj < 4; jj++) o[i][jj] *= al;
            *(float4*)&Ps[ty * 4 + i][tx * 4] =
                make_float4(s[i][0], s[i][1], s[i][2], s[i][3]);
        }
        __syncthreads();

        // O += P @ V
#pragma unroll 8
        for (int kk = 0; kk < 64; kk++) {
            float4 vb = *(const float4*)&Vs[kk][tx * 4];
#pragma unroll
            for (int i = 0; i < 4; i++) {
                float pa = Ps[ty * 4 + i][kk];
                o[i][0] = fmaf(pa, vb.x, o[i][0]);
                o[i][1] = fmaf(pa, vb.y, o[i][1]);
                o[i][2] = fmaf(pa, vb.z, o[i][2]);
                o[i][3] = fmaf(pa, vb.w, o[i][3]);
            }
        }
    }

    // Epilogue: normalize, write att[b, t, h*64 + d]
    float* ob = att + (size_t)(b * Tt + iq * 64) * Cc + h * 64;
#pragma unroll
    for (int i = 0; i < 4; i++) {
        float inv = 1.f / l_i[i];
        *(float4*)(ob + (size_t)(ty * 4 + i) * Cc + tx * 4) =
            make_float4(o[i][0] * inv, o[i][1] * inv, o[i][2] * inv, o[i][3] * inv);
    }
}

// ---------------------------------------------------------------------------
extern "C" void kernel_launch(void* const* d_in, const int* in_sizes, int n_in,
                              void* d_out, int out_size) {
    const float* x = (const float*)d_in[0];      // [B,T,C]
    const float* Wqkv = (const float*)d_in[1];   // [C,3C]
    const float* Wout = (const float*)d_in[2];   // [C,C]
    float* out = (float*)d_out;                  // [B,T,C]

    float* qkv = nullptr;
    float* att = nullptr;
    cudaGetSymbolAddress((void**)&qkv, g_qkv);
    cudaGetSymbolAddress((void**)&att, g_att);

    cudaFuncSetAttribute(flash64, cudaFuncAttributeMaxDynamicSharedMemorySize,
                         FLASH_SMEM);

    // 1) qkv = x @ W_qkv      (M=8192, N=3072, K=1024)
    sgemm128<<<dim3(3072 / 128, 8192 / 128), 256>>>(x, Wqkv, qkv, 3072, 1024);
    // 2) RoPE in place on q,k
    rope_kernel<<<Bb * Tt, 512>>>(qkv);
    // 3) causal flash attention -> att[b,t,h*D+d]
    flash64<<<dim3(Tt / 64, Bb * Hh), 256, FLASH_SMEM>>>(qkv, att);
    // 4) out = att @ W_out    (M=8192, N=1024, K=1024)
    sgemm128<<<dim3(1024 / 128, 8192 / 128), 256>>>(att, Wout, out, 1024, 1024);
}

// round 4
// speedup vs baseline: 1.6716x; 1.6716x over previous
#include <cuda_runtime.h>
#include <math.h>
#include <stdint.h>

#define Bb 4
#define Tt 2048
#define Cc 1024
#define Hh 16
#define Dd 64

// Scratch (no cudaMalloc allowed)
__device__ float g_qkv[Bb * Tt * 3 * Cc];          // 100.7MB
__device__ float g_att[Bb * Tt * Cc];              // 33.5MB (tf32-rounded)
__device__ float g_tf[Bb * Tt * Cc + Cc * 3 * Cc + Cc * Cc];  // x_tf, Wqkv_tf, Wout_tf

#define X_TF_OFF 0
#define WQKV_TF_OFF (Bb * Tt * Cc)
#define WOUT_TF_OFF (Bb * Tt * Cc + Cc * 3 * Cc)

__device__ __forceinline__ float to_tf32(float x) {
    uint32_t u;
    asm("cvt.rna.tf32.f32 %0, %1;" : "=r"(u) : "f"(x));
    return __uint_as_float(u);
}

// ---------------------------------------------------------------------------
// Elementwise round-to-nearest tf32 (stored as f32 bit pattern).
// ---------------------------------------------------------------------------
__global__ __launch_bounds__(256) void round_tf32(const float* __restrict__ in,
                                                  float* __restrict__ out, int n4) {
    int i = blockIdx.x * blockDim.x + threadIdx.x;
    if (i < n4) {
        float4 v = ((const float4*)in)[i];
        v.x = to_tf32(v.x); v.y = to_tf32(v.y);
        v.z = to_tf32(v.z); v.w = to_tf32(v.w);
        ((float4*)out)[i] = v;
    }
}

// ---------------------------------------------------------------------------
// TF32 tensor-core SGEMM: C[M,N] = A[M,K] @ B[K,N], row-major fp32 storage
// (values pre-rounded to tf32). Block 128x128, Ktile 16, 4-stage cp.async
// pipeline, 8 warps, warp tile 64x32 via mma.sync.m16n8k8.tf32.
// M = 8192, K = 1024, N in {3072, 1024}.
// ---------------------------------------------------------------------------
#define STAGES 4
#define KT 16
#define AS_F (128 * 20)      // A stage: 128 rows x 20 floats (16 + 4 pad)
#define BS_F (16 * 136)      // B stage: 16 rows x 136 floats (128 + 8 pad)
#define STAGE_F (AS_F + BS_F)
#define GEMM_SMEM (STAGES * STAGE_F * 4)

__device__ __forceinline__ void cp16(uint32_t saddr, const float* gaddr) {
    asm volatile("cp.async.cg.shared.global [%0], [%1], 16;\n" ::"r"(saddr), "l"(gaddr));
}

__global__ __launch_bounds__(256, 2) void sgemm_tf32(const float* __restrict__ A,
                                                     const float* __restrict__ Bm,
                                                     float* __restrict__ Cm,
                                                     int N, int K) {
    extern __shared__ float smem[];
    const int tid = threadIdx.x;
    const int warp = tid >> 5, lane = tid & 31;
    const int wm = warp & 1, wn = warp >> 1;      // 2 x 4 warp grid
    const int g = lane >> 2, t = lane & 3;
    const size_t m0 = (size_t)blockIdx.y * 128;
    const int n0 = blockIdx.x * 128;
    const int NT = K / KT;                        // 64

    // loader assignment
    const int a_mm = tid >> 2;                    // 0..63 (+64 for 2nd chunk)
    const int a_kk4 = (tid & 3) << 2;             // 0,4,8,12
    const int b_kk = tid >> 5;                    // 0..7 (+8 for 2nd chunk)
    const int b_nn4 = (tid & 31) << 2;            // 0..124

    const float* Ab = A + (m0 + a_mm) * (size_t)K + a_kk4;
    const float* Bc = Bm + (size_t)b_kk * N + n0 + b_nn4;

    const uint32_t smem_base = (uint32_t)__cvta_generic_to_shared(smem);

#define ISSUE_TILE(kt)                                                          \
    do {                                                                        \
        int s_ = (kt) & (STAGES - 1);                                           \
        uint32_t as_ = smem_base + (s_ * STAGE_F) * 4;                          \
        uint32_t bs_ = as_ + AS_F * 4;                                          \
        cp16(as_ + (a_mm * 20 + a_kk4) * 4, Ab + (size_t)(kt) * KT);            \
        cp16(as_ + ((a_mm + 64) * 20 + a_kk4) * 4,                              \
             Ab + 64 * (size_t)K + (size_t)(kt) * KT);                          \
        cp16(bs_ + (b_kk * 136 + b_nn4) * 4, Bc + (size_t)(kt) * KT * N);       \
        cp16(bs_ + ((b_kk + 8) * 136 + b_nn4) * 4,                              \
             Bc + ((size_t)(kt) * KT + 8) * N);                                 \
    } while (0)

    // prologue: tiles 0,1,2
    ISSUE_TILE(0);
    asm volatile("cp.async.commit_group;\n");
    ISSUE_TILE(1);
    asm volatile("cp.async.commit_group;\n");
    ISSUE_TILE(2);
    asm volatile("cp.async.commit_group;\n");

    float acc[4][4][4];
#pragma unroll
    for (int i = 0; i < 4; i++)
#pragma unroll
        for (int j = 0; j < 4; j++)
#pragma unroll
            for (int r = 0; r < 4; r++) acc[i][j][r] = 0.f;

    for (int kt = 0; kt < NT; kt++) {
        asm volatile("cp.async.wait_group %0;\n" ::"n"(2));
        __syncthreads();

        if (kt + 3 < NT) ISSUE_TILE(kt + 3);
        asm volatile("cp.async.commit_group;\n");   // unconditional: keeps count uniform

        const float* As = smem + (kt & (STAGES - 1)) * STAGE_F;
        const float* Bs = As + AS_F;

#pragma unroll
        for (int s8 = 0; s8 < 2; s8++) {
            uint32_t af[4][4], bf[4][2];
#pragma unroll
            for (int i = 0; i < 4; i++) {
                int row = wm * 64 + i * 16;
                int kc = s8 * 8 + t;
                af[i][0] = __float_as_uint(As[(row + g) * 20 + kc]);
                af[i][1] = __float_as_uint(As[(row + g + 8) * 20 + kc]);
                af[i][2] = __float_as_uint(As[(row + g) * 20 + kc + 4]);
                af[i][3] = __float_as_uint(As[(row + g + 8) * 20 + kc + 4]);
            }
#pragma unroll
            for (int j = 0; j < 4; j++) {
                int col = wn * 32 + j * 8 + g;
                bf[j][0] = __float_as_uint(Bs[(s8 * 8 + t) * 136 + col]);
                bf[j][1] = __float_as_uint(Bs[(s8 * 8 + t + 4) * 136 + col]);
            }
#pragma unroll
            for (int i = 0; i < 4; i++)
#pragma unroll
                for (int j = 0; j < 4; j++) {
                    asm volatile(
                        "mma.sync.aligned.m16n8k8.row.col.f32.tf32.tf32.f32 "
                        "{%0,%1,%2,%3}, {%4,%5,%6,%7}, {%8,%9}, {%0,%1,%2,%3};"
                        : "+f"(acc[i][j][0]), "+f"(acc[i][j][1]),
                          "+f"(acc[i][j][2]), "+f"(acc[i][j][3])
                        : "r"(af[i][0]), "r"(af[i][1]), "r"(af[i][2]), "r"(af[i][3]),
                          "r"(bf[j][0]), "r"(bf[j][1]));
                }
        }
    }

    // epilogue: fragment layout c0:(g,2t) c1:(g,2t+1) c2:(g+8,2t) c3:(g+8,2t+1)
#pragma unroll
    for (int i = 0; i < 4; i++) {
#pragma unroll
        for (int j = 0; j < 4; j++) {
            size_t row = m0 + wm * 64 + i * 16 + g;
            int col = n0 + wn * 32 + j * 8 + 2 * t;
            *(float2*)(Cm + row * N + col) = make_float2(acc[i][j][0], acc[i][j][1]);
            *(float2*)(Cm + (row + 8) * N + col) = make_float2(acc[i][j][2], acc[i][j][3]);
        }
    }
#undef ISSUE_TILE
}

// ---------------------------------------------------------------------------
// RoPE in-place on q and k sections of g_qkv (unchanged from R1).
// ---------------------------------------------------------------------------
__global__ __launch_bounds__(512) void rope_kernel(float* __restrict__ qkv) {
    __shared__ float sc[32], ss[32];
    const int bt = blockIdx.x;
    const int t = bt & (Tt - 1);
    const int j = threadIdx.x;
    if (j < 32) {
        double invf = pow(10000.0, -(double)j / 32.0);
        double a = (double)t * invf;
        sc[j] = (float)cos(a);
        ss[j] = (float)sin(a);
    }
    __syncthreads();
    const int h = j >> 5;
    const int i = j & 31;
    const float c = sc[i], s = ss[i];
    float2* qp = (float2*)(qkv + (size_t)bt * 3072 + h * 64);
    float2 q = qp[i];
    qp[i] = make_float2(q.x * c - q.y * s, q.y * c + q.x * s);
    float2* kp = (float2*)(qkv + (size_t)bt * 3072 + 1024 + h * 64);
    float2 k = kp[i];
    kp[i] = make_float2(k.x * c - k.y * s, k.y * c + k.x * s);
}

// ---------------------------------------------------------------------------
// Causal flash attention, fp32 (unchanged from R1 except epilogue rounds the
// output to tf32 so the out-proj GEMM can consume it directly).
// ---------------------------------------------------------------------------
#define FLASH_SMEM ((3 * 64 * 64 + 64 * 68) * 4)

__global__ __launch_bounds__(256) void flash64(const float* __restrict__ qkv,
                                               float* __restrict__ att) {
    extern __shared__ float sm[];
    float(*Qs)[64] = (float(*)[64])sm;
    float(*Ks)[64] = (float(*)[64])(sm + 64 * 64);
    float(*Vs)[64] = (float(*)[64])(sm + 2 * 64 * 64);
    float(*Ps)[68] = (float(*)[68])(sm + 3 * 64 * 64);

    const int iq = blockIdx.x;
    const int bh = blockIdx.y;
    const int b = bh >> 4;
    const int h = bh & 15;
    const int tid = threadIdx.x;
    const int tx = tid & 15;
    const int ty = tid >> 4;

    const float* base = qkv + (size_t)b * Tt * 3072 + h * 64;

    {
        const int r = tid & 63;
        const int c4base = tid >> 6;
        const float* qrow = base + (size_t)(iq * 64 + r) * 3072;
#pragma unroll
        for (int rep = 0; rep < 4; rep++) {
            int c4 = c4base + rep * 4;
            float4 v = *(const float4*)(qrow + c4 * 4);
            Qs[c4 * 4 + 0][r] = v.x * 0.125f;
            Qs[c4 * 4 + 1][r] = v.y * 0.125f;
            Qs[c4 * 4 + 2][r] = v.z * 0.125f;
            Qs[c4 * 4 + 3][r] = v.w * 0.125f;
        }
    }

    float o[4][4];
    float m_i[4], l_i[4];
#pragma unroll
    for (int i = 0; i < 4; i++) {
        m_i[i] = -1e30f;
        l_i[i] = 0.f;
#pragma unroll
        for (int j = 0; j < 4; j++) o[i][j] = 0.f;
    }

    for (int jt = 0; jt <= iq; jt++) {
        __syncthreads();
        {
            const int r = tid & 63;
            const int c4base = tid >> 6;
            const float* krow = base + (size_t)(jt * 64 + r) * 3072 + 1024;
#pragma unroll
            for (int rep = 0; rep < 4; rep++) {
                int c4 = c4base + rep * 4;
                float4 kv = *(const float4*)(krow + c4 * 4);
                Ks[c4 * 4 + 0][r] = kv.x;
                Ks[c4 * 4 + 1][r] = kv.y;
                Ks[c4 * 4 + 2][r] = kv.z;
                Ks[c4 * 4 + 3][r] = kv.w;
            }
#pragma unroll
            for (int rep = 0; rep < 4; rep++) {
                int idx = tid + rep * 256;
                int rv = idx >> 4;
                int cv = (idx & 15) << 2;
                *(float4*)&Vs[rv][cv] =
                    *(const float4*)(base + (size_t)(jt * 64 + rv) * 3072 + 2048 + cv);
            }
        }
        __syncthreads();

        float s[4][4];
#pragma unroll
        for (int i = 0; i < 4; i++)
#pragma unroll
            for (int jj = 0; jj < 4; jj++) s[i][jj] = 0.f;

#pragma unroll 8
        for (int kk = 0; kk < 64; kk++) {
            float4 qa = *(const float4*)&Qs[kk][ty * 4];
            float4 kb = *(const float4*)&Ks[kk][tx * 4];
            float ra[4] = {qa.x, qa.y, qa.z, qa.w};
            float rb[4] = {kb.x, kb.y, kb.z, kb.w};
#pragma unroll
            for (int i = 0; i < 4; i++)
#pragma unroll
                for (int jj = 0; jj < 4; jj++)
                    s[i][jj] = fmaf(ra[i], rb[jj], s[i][jj]);
        }

        if (jt == iq) {
#pragma unroll
            for (int i = 0; i < 4; i++)
#pragma unroll
                for (int jj = 0; jj < 4; jj++)
                    if (tx * 4 + jj > ty * 4 + i) s[i][jj] = -1e30f;
        }

#pragma unroll
        for (int i = 0; i < 4; i++) {
            float rmax = fmaxf(fmaxf(s[i][0], s[i][1]), fmaxf(s[i][2], s[i][3]));
#pragma unroll
            for (int off = 8; off >= 1; off >>= 1)
                rmax = fmaxf(rmax, __shfl_xor_sync(0xffffffffu, rmax, off, 16));
            float mnew = fmaxf(m_i[i], rmax);
            float al = __expf(m_i[i] - mnew);
            float rs = 0.f;
#pragma unroll
            for (int jj = 0; jj < 4; jj++) {
                s[i][jj] = __expf(s[i][jj] - mnew);
                rs += s[i][jj];
            }
#pragma unroll
            for (int off = 8; off >= 1; off >>= 1)
                rs += __shfl_xor_sync(0xffffffffu, rs, off, 16);
            l_i[i] = l_i[i] * al + rs;
            m_i[i] = mnew;
#pragma unroll
            for (int jj = 0; jj < 4; jj++) o[i][jj] *= al;
            *(float4*)&Ps[ty * 4 + i][tx * 4] =
                make_float4(s[i][0], s[i][1], s[i][2], s[i][3]);
        }
        __syncthreads();

#pragma unroll 8
        for (int kk = 0; kk < 64; kk++) {
            float4 vb = *(const float4*)&Vs[kk][tx * 4];
#pragma unroll
            for (int i = 0; i < 4; i++) {
                float pa = Ps[ty * 4 + i][kk];
                o[i][0] = fmaf(pa, vb.x, o[i][0]);
                o[i][1] = fmaf(pa, vb.y, o[i][1]);
                o[i][2] = fmaf(pa, vb.z, o[i][2]);
                o[i][3] = fmaf(pa, vb.w, o[i][3]);
            }
        }
    }

    float* ob = att + (size_t)(b * Tt + iq * 64) * Cc + h * 64;
#pragma unroll
    for (int i = 0; i < 4; i++) {
        float inv = 1.f / l_i[i];
        *(float4*)(ob + (size_t)(ty * 4 + i) * Cc + tx * 4) =
            make_float4(to_tf32(o[i][0] * inv), to_tf32(o[i][1] * inv),
                        to_tf32(o[i][2] * inv), to_tf32(o[i][3] * inv));
    }
}

// ---------------------------------------------------------------------------
extern "C" void kernel_launch(void* const* d_in, const int* in_sizes, int n_in,
                              void* d_out, int out_size) {
    const float* x = (const float*)d_in[0];      // [B,T,C]
    const float* Wqkv = (const float*)d_in[1];   // [C,3C]
    const float* Wout = (const float*)d_in[2];   // [C,C]
    float* out = (float*)d_out;                  // [B,T,C]

    float* qkv = nullptr;
    float* att = nullptr;
    float* tf = nullptr;
    cudaGetSymbolAddress((void**)&qkv, g_qkv);
    cudaGetSymbolAddress((void**)&att, g_att);
    cudaGetSymbolAddress((void**)&tf, g_tf);

    float* x_tf = tf + X_TF_OFF;
    float* wqkv_tf = tf + WQKV_TF_OFF;
    float* wout_tf = tf + WOUT_TF_OFF;

    cudaFuncSetAttribute(flash64, cudaFuncAttributeMaxDynamicSharedMemorySize,
                         FLASH_SMEM);
    cudaFuncSetAttribute(sgemm_tf32, cudaFuncAttributeMaxDynamicSharedMemorySize,
                         GEMM_SMEM);

    // 0) round inputs to tf32
    {
        int n4;
        n4 = (Bb * Tt * Cc) / 4;
        round_tf32<<<(n4 + 255) / 256, 256>>>(x, x_tf, n4);
        n4 = (Cc * 3 * Cc) / 4;
        round_tf32<<<(n4 + 255) / 256, 256>>>(Wqkv, wqkv_tf, n4);
        n4 = (Cc * Cc) / 4;
        round_tf32<<<(n4 + 255) / 256, 256>>>(Wout, wout_tf, n4);
    }

    // 1) qkv = x @ W_qkv      (M=8192, N=3072, K=1024) — tf32 tensor cores
    sgemm_tf32<<<dim3(3072 / 128, 8192 / 128), 256, GEMM_SMEM>>>(x_tf, wqkv_tf, qkv,
                                                                 3072, 1024);
    // 2) RoPE in place on q,k
    rope_kernel<<<Bb * Tt, 512>>>(qkv);
    // 3) causal flash attention -> att (tf32-rounded)
    flash64<<<dim3(Tt / 64, Bb * Hh), 256, FLASH_SMEM>>>(qkv, att);
    // 4) out = att @ W_out    (M=8192, N=1024, K=1024) — tf32 tensor cores
    sgemm_tf32<<<dim3(1024 / 128, 8192 / 128), 256, GEMM_SMEM>>>(att, wout_tf, out,
                                                                 1024, 1024);
}

// round 9
// speedup vs baseline: 4.0173x; 2.4032x over previous
#include <cuda_runtime.h>
#include <cuda_fp16.h>
#include <math.h>
#include <stdint.h>

#define Bb 4
#define Tt 2048
#define Cc 1024
#define Hh 16
#define Dd 64
#define BTC (Bb * Tt * Cc)

// Scratch (no cudaMalloc allowed)
__device__ float g_qkv[Bb * Tt * 3 * Cc];                     // 100.7MB
__device__ float g_att[BTC];                                  // 33.5MB
__device__ float g_tf[BTC + Cc * 3 * Cc + Cc * Cc];           // tf32 inputs
__device__ __half g_h[3 * BTC];                               // q16,k16,v16t
__device__ float g_rope[Tt * 64];                             // cos/sin table

#define X_TF_OFF 0
#define WQKV_TF_OFF BTC
#define WOUT_TF_OFF (BTC + Cc * 3 * Cc)

__device__ __forceinline__ float to_tf32(float x) {
    uint32_t u;
    asm("cvt.rna.tf32.f32 %0, %1;" : "=r"(u) : "f"(x));
    return __uint_as_float(u);
}

__device__ __forceinline__ void cp16(uint32_t saddr, const void* gaddr) {
    asm volatile("cp.async.cg.shared.global [%0], [%1], 16;\n" ::"r"(saddr), "l"(gaddr));
}

// ---------------------------------------------------------------------------
__global__ __launch_bounds__(256) void round_tf32(const float* __restrict__ in,
                                                  float* __restrict__ out, int n4) {
    int i = blockIdx.x * blockDim.x + threadIdx.x;
    if (i < n4) {
        float4 v = ((const float4*)in)[i];
        v.x = to_tf32(v.x); v.y = to_tf32(v.y);
        v.z = to_tf32(v.z); v.w = to_tf32(v.w);
        ((float4*)out)[i] = v;
    }
}

// ---------------------------------------------------------------------------
// RoPE cos/sin table, double precision trig. grid=T, 32 threads.
// ---------------------------------------------------------------------------
__global__ void rope_table_k(float* __restrict__ tab) {
    int t = blockIdx.x;
    int i = threadIdx.x;
    double invf = pow(10000.0, -(double)i / 32.0);
    double a = (double)t * invf;
    tab[t * 64 + 2 * i] = (float)cos(a);
    tab[t * 64 + 2 * i + 1] = (float)sin(a);
}

// ---------------------------------------------------------------------------
// TF32 tensor-core SGEMM (unchanged).
// ---------------------------------------------------------------------------
#define STAGES 4
#define KT 16
#define AS_F (128 * 20)
#define BS_F (16 * 136)
#define STAGE_F (AS_F + BS_F)
#define GEMM_SMEM (STAGES * STAGE_F * 4)

__global__ __launch_bounds__(256, 2) void sgemm_tf32(const float* __restrict__ A,
                                                     const float* __restrict__ Bm,
                                                     float* __restrict__ Cm,
                                                     int N, int K) {
    extern __shared__ float smem[];
    const int tid = threadIdx.x;
    const int warp = tid >> 5, lane = tid & 31;
    const int wm = warp & 1, wn = warp >> 1;
    const int g = lane >> 2, t = lane & 3;
    const size_t m0 = (size_t)blockIdx.y * 128;
    const int n0 = blockIdx.x * 128;
    const int NT = K / KT;

    const int a_mm = tid >> 2;
    const int a_kk4 = (tid & 3) << 2;
    const int b_kk = tid >> 5;
    const int b_nn4 = (tid & 31) << 2;

    const float* Ab = A + (m0 + a_mm) * (size_t)K + a_kk4;
    const float* Bc = Bm + (size_t)b_kk * N + n0 + b_nn4;

    const uint32_t smem_base = (uint32_t)__cvta_generic_to_shared(smem);

#define ISSUE_TILE(kt)                                                          \
    do {                                                                        \
        int s_ = (kt) & (STAGES - 1);                                           \
        uint32_t as_ = smem_base + (s_ * STAGE_F) * 4;                          \
        uint32_t bs_ = as_ + AS_F * 4;                                          \
        cp16(as_ + (a_mm * 20 + a_kk4) * 4, Ab + (size_t)(kt) * KT);            \
        cp16(as_ + ((a_mm + 64) * 20 + a_kk4) * 4,                              \
             Ab + 64 * (size_t)K + (size_t)(kt) * KT);                          \
        cp16(bs_ + (b_kk * 136 + b_nn4) * 4, Bc + (size_t)(kt) * KT * N);       \
        cp16(bs_ + ((b_kk + 8) * 136 + b_nn4) * 4,                              \
             Bc + ((size_t)(kt) * KT + 8) * N);                                 \
    } while (0)

    ISSUE_TILE(0);
    asm volatile("cp.async.commit_group;\n");
    ISSUE_TILE(1);
    asm volatile("cp.async.commit_group;\n");
    ISSUE_TILE(2);
    asm volatile("cp.async.commit_group;\n");

    float acc[4][4][4];
#pragma unroll
    for (int i = 0; i < 4; i++)
#pragma unroll
        for (int j = 0; j < 4; j++)
#pragma unroll
            for (int r = 0; r < 4; r++) acc[i][j][r] = 0.f;

    for (int kt = 0; kt < NT; kt++) {
        asm volatile("cp.async.wait_group %0;\n" ::"n"(2));
        __syncthreads();

        if (kt + 3 < NT) ISSUE_TILE(kt + 3);
        asm volatile("cp.async.commit_group;\n");

        const float* As = smem + (kt & (STAGES - 1)) * STAGE_F;
        const float* Bs = As + AS_F;

#pragma unroll
        for (int s8 = 0; s8 < 2; s8++) {
            uint32_t af[4][4], bf[4][2];
#pragma unroll
            for (int i = 0; i < 4; i++) {
                int row = wm * 64 + i * 16;
                int kc = s8 * 8 + t;
                af[i][0] = __float_as_uint(As[(row + g) * 20 + kc]);
                af[i][1] = __float_as_uint(As[(row + g + 8) * 20 + kc]);
                af[i][2] = __float_as_uint(As[(row + g) * 20 + kc + 4]);
                af[i][3] = __float_as_uint(As[(row + g + 8) * 20 + kc + 4]);
            }
#pragma unroll
            for (int j = 0; j < 4; j++) {
                int col = wn * 32 + j * 8 + g;
                bf[j][0] = __float_as_uint(Bs[(s8 * 8 + t) * 136 + col]);
                bf[j][1] = __float_as_uint(Bs[(s8 * 8 + t + 4) * 136 + col]);
            }
#pragma unroll
            for (int i = 0; i < 4; i++)
#pragma unroll
                for (int j = 0; j < 4; j++) {
                    asm volatile(
                        "mma.sync.aligned.m16n8k8.row.col.f32.tf32.tf32.f32 "
                        "{%0,%1,%2,%3}, {%4,%5,%6,%7}, {%8,%9}, {%0,%1,%2,%3};"
                        : "+f"(acc[i][j][0]), "+f"(acc[i][j][1]),
                          "+f"(acc[i][j][2]), "+f"(acc[i][j][3])
                        : "r"(af[i][0]), "r"(af[i][1]), "r"(af[i][2]), "r"(af[i][3]),
                          "r"(bf[j][0]), "r"(bf[j][1]));
                }
        }
    }

#pragma unroll
    for (int i = 0; i < 4; i++) {
#pragma unroll
        for (int j = 0; j < 4; j++) {
            size_t row = m0 + wm * 64 + i * 16 + g;
            int col = n0 + wn * 32 + j * 8 + 2 * t;
            *(float2*)(Cm + row * N + col) = make_float2(acc[i][j][0], acc[i][j][1]);
            *(float2*)(Cm + (row + 8) * N + col) = make_float2(acc[i][j][2], acc[i][j][3]);
        }
    }
#undef ISSUE_TILE
}

// ---------------------------------------------------------------------------
// prep16: RoPE + fp16 convert. Per block: one (b,h) x 64-token tile.
// q16,k16: [b,h,t,d] halves (q pre-scaled 0.125); v16t: [b,h,d,t] halves.
// FIX (R6): transpose writeout now covers all 64 tokens (2 float4 per thread;
// previously seg stride 16 with one float4 -> half of v16t left zero).
// ---------------------------------------------------------------------------
#define QS_H 72

__global__ __launch_bounds__(256) void prep16(const float* __restrict__ qkv,
                                              const float* __restrict__ tab,
                                              __half* __restrict__ q16,
                                              __half* __restrict__ k16,
                                              __half* __restrict__ v16t) {
    __shared__ __half vts[64 * QS_H];
    const int tt = blockIdx.x, bh = blockIdx.y;
    const int b = bh >> 4, h = bh & 15;
    const int t0 = tt * 64;
    const int tid = threadIdx.x;

#pragma unroll
    for (int p = 0; p < 8; p++) {
        int idx = tid + p * 256;
        int tl = idx >> 5, i = idx & 31;
        const float* base =
            qkv + ((size_t)(b * Tt + t0 + tl)) * 3072 + h * 64 + 2 * i;
        float2 cs = *(const float2*)(tab + (t0 + tl) * 64 + 2 * i);
        float2 q = *(const float2*)(base);
        float2 k = *(const float2*)(base + 1024);
        float2 v = *(const float2*)(base + 2048);
        float qr0 = (q.x * cs.x - q.y * cs.y) * 0.125f;
        float qr1 = (q.y * cs.x + q.x * cs.y) * 0.125f;
        float kr0 = k.x * cs.x - k.y * cs.y;
        float kr1 = k.y * cs.x + k.x * cs.y;
        size_t o = ((size_t)bh * Tt + t0 + tl) * 32 + i;
        ((__half2*)q16)[o] = __floats2half2_rn(qr0, qr1);
        ((__half2*)k16)[o] = __floats2half2_rn(kr0, kr1);
        vts[(2 * i) * QS_H + tl] = __float2half_rn(v.x);
        vts[(2 * i + 1) * QS_H + tl] = __float2half_rn(v.y);
    }
    __syncthreads();
    const int d = tid >> 2, seg = tid & 3;
    float4 v0 = *(const float4*)&vts[d * QS_H + seg * 16];
    float4 v1 = *(const float4*)&vts[d * QS_H + seg * 16 + 8];
    __half* dst = v16t + ((size_t)bh * 64 + d) * Tt + t0 + seg * 16;
    *(float4*)dst = v0;
    *(float4*)(dst + 8) = v1;
}

// ---------------------------------------------------------------------------
// flash16: fp16 tensor-core causal flash attention (FA2-style).
// BM=128, BN=64, 256 threads (8 warps x 16 rows). Double-buffered cp.async.
// Output att [b,t,h*64+d] fp32, tf32-rounded for the out-proj GEMM.
// ---------------------------------------------------------------------------
#define FL_SMEM ((9216 + 2 * 9216) * 2)   // Q + 2 stages of (K+V), halves*2B

__global__ __launch_bounds__(256, 2) void flash16(const __half* __restrict__ q16,
                                                  const __half* __restrict__ k16,
                                                  const __half* __restrict__ v16t,
                                                  float* __restrict__ att) {
    extern __shared__ __half hs[];
    const int iq = gridDim.x - 1 - blockIdx.x;   // heavy blocks first
    const int bh = blockIdx.y;
    const int b = bh >> 4, h = bh & 15;
    const int tid = threadIdx.x;
    const int w = tid >> 5, lane = tid & 31;
    const int g = lane >> 2, t = lane & 3;
    const int wr = w * 16;
    const size_t tbase = (size_t)bh * Tt;
    const uint32_t sb = (uint32_t)__cvta_generic_to_shared(hs);
    const int jmax = 2 * iq + 1;

#define ISSUE_KV(jt, s)                                                          \
    do {                                                                         \
        int row_ = tid >> 2;                                                     \
        int cb_ = tid & 3;                                                       \
        const __half* gk_ = k16 + (tbase + (jt)*64 + row_) * 64;                 \
        const __half* gv_ = v16t + ((size_t)bh * 64 + row_) * Tt + (jt)*64;      \
        uint32_t sk_ = sb + (9216 + (s)*9216 + row_ * QS_H) * 2;                 \
        uint32_t sv_ = sk_ + 4608 * 2;                                           \
        cp16(sk_ + cb_ * 16, gk_ + cb_ * 8);                                     \
        cp16(sk_ + (cb_ + 4) * 16, gk_ + (cb_ + 4) * 8);                         \
        cp16(sv_ + cb_ * 16, gv_ + cb_ * 8);                                     \
        cp16(sv_ + (cb_ + 4) * 16, gv_ + (cb_ + 4) * 8);                         \
    } while (0)

    // prologue: Q tile + KV tile 0 as one group
    {
        int row = tid >> 1;
        int cb = tid & 1;
        const __half* gq = q16 + (tbase + iq * 128 + row) * 64;
        uint32_t sq = sb + (row * QS_H) * 2;
#pragma unroll
        for (int c = cb; c < 8; c += 2) cp16(sq + c * 16, gq + c * 8);
    }
    ISSUE_KV(0, 0);
    asm volatile("cp.async.commit_group;\n");

    float oacc[8][4];
    float m0 = -1e30f, m1 = -1e30f, l0 = 0.f, l1 = 0.f;
#pragma unroll
    for (int ds = 0; ds < 8; ds++)
#pragma unroll
        for (int r = 0; r < 4; r++) oacc[ds][r] = 0.f;

    uint32_t qf[4][4];
    bool qf_loaded = false;

    for (int jt = 0; jt <= jmax; jt++) {
        if (jt + 1 <= jmax) ISSUE_KV(jt + 1, (jt + 1) & 1);
        asm volatile("cp.async.commit_group;\n");
        asm volatile("cp.async.wait_group %0;\n" ::"n"(1));
        __syncthreads();

        if (!qf_loaded) {   // Q frags (Qs ready after first wait)
            qf_loaded = true;
#pragma unroll
            for (int kc = 0; kc < 4; kc++) {
                qf[kc][0] = *(const uint32_t*)&hs[(wr + g) * QS_H + kc * 16 + 2 * t];
                qf[kc][1] = *(const uint32_t*)&hs[(wr + g + 8) * QS_H + kc * 16 + 2 * t];
                qf[kc][2] = *(const uint32_t*)&hs[(wr + g) * QS_H + kc * 16 + 2 * t + 8];
                qf[kc][3] = *(const uint32_t*)&hs[(wr + g + 8) * QS_H + kc * 16 + 2 * t + 8];
            }
        }

        const __half* Ks = hs + 9216 + (jt & 1) * 9216;
        const __half* Vs = Ks + 4608;

        // S = Q @ K^T
        float sa[8][4];
#pragma unroll
        for (int ns = 0; ns < 8; ns++)
#pragma unroll
            for (int r = 0; r < 4; r++) sa[ns][r] = 0.f;

#pragma unroll
        for (int kc = 0; kc < 4; kc++)
#pragma unroll
            for (int ns = 0; ns < 8; ns++) {
                uint32_t b0 = *(const uint32_t*)&Ks[(ns * 8 + g) * QS_H + kc * 16 + 2 * t];
                uint32_t b1 = *(const uint32_t*)&Ks[(ns * 8 + g) * QS_H + kc * 16 + 2 * t + 8];
                asm volatile(
                    "mma.sync.aligned.m16n8k16.row.col.f32.f16.f16.f32 "
                    "{%0,%1,%2,%3}, {%4,%5,%6,%7}, {%8,%9}, {%0,%1,%2,%3};"
                    : "+f"(sa[ns][0]), "+f"(sa[ns][1]), "+f"(sa[ns][2]), "+f"(sa[ns][3])
                    : "r"(qf[kc][0]), "r"(qf[kc][1]), "r"(qf[kc][2]), "r"(qf[kc][3]),
                      "r"(b0), "r"(b1));
            }

        // causal mask (only last two tiles touch the diagonal)
        if (jt >= 2 * iq) {
            const int row0 = iq * 128 + wr + g;
            const int row1 = row0 + 8;
#pragma unroll
            for (int ns = 0; ns < 8; ns++) {
                int c0 = jt * 64 + ns * 8 + 2 * t;
                if (c0 > row0) sa[ns][0] = -1e30f;
                if (c0 + 1 > row0) sa[ns][1] = -1e30f;
                if (c0 > row1) sa[ns][2] = -1e30f;
                if (c0 + 1 > row1) sa[ns][3] = -1e30f;
            }
        }

        // online softmax (rows g and g+8; quad reduction)
        {
            float mx0 = -1e30f, mx1 = -1e30f;
#pragma unroll
            for (int ns = 0; ns < 8; ns++) {
                mx0 = fmaxf(mx0, fmaxf(sa[ns][0], sa[ns][1]));
                mx1 = fmaxf(mx1, fmaxf(sa[ns][2], sa[ns][3]));
            }
#pragma unroll
            for (int off = 1; off <= 2; off <<= 1) {
                mx0 = fmaxf(mx0, __shfl_xor_sync(0xffffffffu, mx0, off));
                mx1 = fmaxf(mx1, __shfl_xor_sync(0xffffffffu, mx1, off));
            }
            float mn0 = fmaxf(m0, mx0), mn1 = fmaxf(m1, mx1);
            float al0 = __expf(m0 - mn0), al1 = __expf(m1 - mn1);
            float s0 = 0.f, s1 = 0.f;
#pragma unroll
            for (int ns = 0; ns < 8; ns++) {
                sa[ns][0] = __expf(sa[ns][0] - mn0);
                sa[ns][1] = __expf(sa[ns][1] - mn0);
                sa[ns][2] = __expf(sa[ns][2] - mn1);
                sa[ns][3] = __expf(sa[ns][3] - mn1);
                s0 += sa[ns][0] + sa[ns][1];
                s1 += sa[ns][2] + sa[ns][3];
            }
#pragma unroll
            for (int off = 1; off <= 2; off <<= 1) {
                s0 += __shfl_xor_sync(0xffffffffu, s0, off);
                s1 += __shfl_xor_sync(0xffffffffu, s1, off);
            }
            l0 = l0 * al0 + s0;
            l1 = l1 * al1 + s1;
            m0 = mn0;
            m1 = mn1;
#pragma unroll
            for (int ds = 0; ds < 8; ds++) {
                oacc[ds][0] *= al0;
                oacc[ds][1] *= al0;
                oacc[ds][2] *= al1;
                oacc[ds][3] *= al1;
            }
        }

        // P -> fp16 A-frags (direct register reuse; C->A layout identity)
        uint32_t pf[4][4];
#pragma unroll
        for (int kc = 0; kc < 4; kc++) {
            __half2 h0 = __floats2half2_rn(sa[2 * kc][0], sa[2 * kc][1]);
            __half2 h1 = __floats2half2_rn(sa[2 * kc][2], sa[2 * kc][3]);
            __half2 h2 = __floats2half2_rn(sa[2 * kc + 1][0], sa[2 * kc + 1][1]);
            __half2 h3 = __floats2half2_rn(sa[2 * kc + 1][2], sa[2 * kc + 1][3]);
            pf[kc][0] = *(uint32_t*)&h0;
            pf[kc][1] = *(uint32_t*)&h1;
            pf[kc][2] = *(uint32_t*)&h2;
            pf[kc][3] = *(uint32_t*)&h3;
        }

        // O += P @ V   (V stored transposed: Vs[d][j])
#pragma unroll
        for (int kc = 0; kc < 4; kc++)
#pragma unroll
            for (int ds = 0; ds < 8; ds++) {
                uint32_t b0 = *(const uint32_t*)&Vs[(ds * 8 + g) * QS_H + kc * 16 + 2 * t];
                uint32_t b1 = *(const uint32_t*)&Vs[(ds * 8 + g) * QS_H + kc * 16 + 2 * t + 8];
                asm volatile(
                    "mma.sync.aligned.m16n8k16.row.col.f32.f16.f16.f32 "
                    "{%0,%1,%2,%3}, {%4,%5,%6,%7}, {%8,%9}, {%0,%1,%2,%3};"
                    : "+f"(oacc[ds][0]), "+f"(oacc[ds][1]), "+f"(oacc[ds][2]),
                      "+f"(oacc[ds][3])
                    : "r"(pf[kc][0]), "r"(pf[kc][1]), "r"(pf[kc][2]), "r"(pf[kc][3]),
                      "r"(b0), "r"(b1));
            }

        __syncthreads();   // all warps done reading this stage before reuse
    }

    // epilogue: normalize, tf32-round, write att[b, t, h*64 + d]
    const float il0 = 1.f / l0, il1 = 1.f / l1;
    float* p0 = att + ((size_t)b * Tt + iq * 128 + wr + g) * Cc + h * 64;
    float* p1 = p0 + 8 * (size_t)Cc;
#pragma unroll
    for (int ds = 0; ds < 8; ds++) {
        *(float2*)(p0 + ds * 8 + 2 * t) =
            make_float2(to_tf32(oacc[ds][0] * il0), to_tf32(oacc[ds][1] * il0));
        *(float2*)(p1 + ds * 8 + 2 * t) =
            make_float2(to_tf32(oacc[ds][2] * il1), to_tf32(oacc[ds][3] * il1));
    }
#undef ISSUE_KV
}

// ---------------------------------------------------------------------------
extern "C" void kernel_launch(void* const* d_in, const int* in_sizes, int n_in,
                              void* d_out, int out_size) {
    const float* x = (const float*)d_in[0];
    const float* Wqkv = (const float*)d_in[1];
    const float* Wout = (const float*)d_in[2];
    float* out = (float*)d_out;

    float *qkv = nullptr, *att = nullptr, *tf = nullptr, *rope = nullptr;
    __half* hbuf = nullptr;
    cudaGetSymbolAddress((void**)&qkv, g_qkv);
    cudaGetSymbolAddress((void**)&att, g_att);
    cudaGetSymbolAddress((void**)&tf, g_tf);
    cudaGetSymbolAddress((void**)&hbuf, g_h);
    cudaGetSymbolAddress((void**)&rope, g_rope);

    float* x_tf = tf + X_TF_OFF;
    float* wqkv_tf = tf + WQKV_TF_OFF;
    float* wout_tf = tf + WOUT_TF_OFF;
    __half* q16 = hbuf;
    __half* k16 = hbuf + BTC;
    __half* v16t = hbuf + 2 * BTC;

    cudaFuncSetAttribute(sgemm_tf32, cudaFuncAttributeMaxDynamicSharedMemorySize,
                         GEMM_SMEM);
    cudaFuncSetAttribute(flash16, cudaFuncAttributeMaxDynamicSharedMemorySize,
                         FL_SMEM);

    // 0) tf32-round inputs + rope table
    {
        int n4;
        n4 = BTC / 4;
        round_tf32<<<(n4 + 255) / 256, 256>>>(x, x_tf, n4);
        n4 = (Cc * 3 * Cc) / 4;
        round_tf32<<<(n4 + 255) / 256, 256>>>(Wqkv, wqkv_tf, n4);
        n4 = (Cc * Cc) / 4;
        round_tf32<<<(n4 + 255) / 256, 256>>>(Wout, wout_tf, n4);
        rope_table_k<<<Tt, 32>>>(rope);
    }

    // 1) qkv = x @ W_qkv   (tf32 tensor cores)
    sgemm_tf32<<<dim3(3072 / 128, 8192 / 128), 256, GEMM_SMEM>>>(x_tf, wqkv_tf, qkv,
                                                                 3072, 1024);
    // 2) RoPE + fp16 convert (Q scaled, V transposed)
    prep16<<<dim3(Tt / 64, Bb * Hh), 256>>>(qkv, rope, q16, k16, v16t);
    // 3) fp16 tensor-core causal flash attention
    flash16<<<dim3(Tt / 128, Bb * Hh), 256, FL_SMEM>>>(q16, k16, v16t, att);
    // 4) out = att @ W_out (tf32 tensor cores)
    sgemm_tf32<<<dim3(1024 / 128, 8192 / 128), 256, GEMM_SMEM>>>(att, wout_tf, out,
                                                                 1024, 1024);
}

// round 10
// speedup vs baseline: 5.0188x; 1.2493x over previous
#include <cuda_runtime.h>
#include <cuda_fp16.h>
#include <math.h>
#include <stdint.h>

#define Bb 4
#define Tt 2048
#define Cc 1024
#define Hh 16
#define Dd 64
#define BTC (Bb * Tt * Cc)

// Scratch (no cudaMalloc allowed) — all-half dataflow
__device__ __half g_x16[BTC];                 // x in fp16
__device__ __half g_wqkvT[3 * Cc * Cc];       // W_qkv^T [3072][1024]
__device__ __half g_woutT[Cc * Cc];           // W_out^T [1024][1024]
__device__ __half g_qkv16[3 * BTC];           // qkv (GEMM1 out, half)
__device__ __half g_qh[BTC];                  // q roped+scaled
__device__ __half g_kh[BTC];                  // k roped
__device__ __half g_vt[BTC];                  // v transposed [b,h,d,t]
__device__ __half g_att16[BTC];               // attention out (half)
__device__ float g_rope[Tt * 64];             // cos/sin table

__device__ __forceinline__ void cp16(uint32_t saddr, const void* gaddr) {
    asm volatile("cp.async.cg.shared.global [%0], [%1], 16;\n" ::"r"(saddr), "l"(gaddr));
}

// ---------------------------------------------------------------------------
// fp32 -> fp16 elementwise (4 per thread)
// ---------------------------------------------------------------------------
__global__ __launch_bounds__(256) void f32_to_f16(const float* __restrict__ in,
                                                  __half* __restrict__ out, int n4) {
    int i = blockIdx.x * blockDim.x + threadIdx.x;
    if (i < n4) {
        float4 v = ((const float4*)in)[i];
        ((__half2*)out)[2 * i] = __floats2half2_rn(v.x, v.y);
        ((__half2*)out)[2 * i + 1] = __floats2half2_rn(v.z, v.w);
    }
}

// ---------------------------------------------------------------------------
// Transpose f32 [K][N] -> half [N][K]. 32x32 tiles, block (32,8).
// ---------------------------------------------------------------------------
__global__ __launch_bounds__(256) void transpose_to_half(const float* __restrict__ in,
                                                         __half* __restrict__ out,
                                                         int K, int N) {
    __shared__ float tile[32][33];
    int k0 = blockIdx.y * 32, n0 = blockIdx.x * 32;
#pragma unroll
    for (int r = 0; r < 4; r++) {
        int k = threadIdx.y + r * 8;
        tile[k][threadIdx.x] = in[(size_t)(k0 + k) * N + n0 + threadIdx.x];
    }
    __syncthreads();
#pragma unroll
    for (int r = 0; r < 4; r++) {
        int n = threadIdx.y + r * 8;
        out[(size_t)(n0 + n) * K + k0 + threadIdx.x] =
            __float2half_rn(tile[threadIdx.x][n]);
    }
}

// ---------------------------------------------------------------------------
// RoPE cos/sin table, double precision trig. 256-thread blocks.
// ---------------------------------------------------------------------------
__global__ __launch_bounds__(256) void rope_table_k(float* __restrict__ tab) {
    int idx = blockIdx.x * 256 + threadIdx.x;   // 65536 = T*32
    int t = idx >> 5, i = idx & 31;
    double invf = pow(10000.0, -(double)i / 32.0);
    double a = (double)t * invf;
    tab[t * 64 + 2 * i] = (float)cos(a);
    tab[t * 64 + 2 * i + 1] = (float)sin(a);
}

// ---------------------------------------------------------------------------
// fp16 tensor-core GEMM: C[M,N] = A[M,K] @ Bt[N,K]^T  (A,Bt half row-major).
// Block 128x128, KT=32 halves, 4-stage cp.async, 8 warps (2x4), warp 64x32,
// mma.m16n8k16. HALF_OUT selects half2 vs float2 epilogue.
// ---------------------------------------------------------------------------
#define HSTAGES 4
#define HKT 32
#define HROW 40                       // padded row length (halves)
#define HA_H (128 * HROW)             // 5120 halves per A stage
#define HSTAGE_H (2 * HA_H)           // A + B
#define HGEMM_SMEM (HSTAGES * HSTAGE_H * 2)

template <bool HALF_OUT>
__global__ __launch_bounds__(256, 2) void hgemm(const __half* __restrict__ A,
                                                const __half* __restrict__ Bt,
                                                void* __restrict__ Cm,
                                                int N, int K) {
    extern __shared__ __half hsm[];
    const int tid = threadIdx.x;
    const int warp = tid >> 5, lane = tid & 31;
    const int wm = warp & 1, wn = warp >> 1;
    const int g = lane >> 2, t = lane & 3;
    const size_t m0 = (size_t)blockIdx.y * 128;
    const int n0 = blockIdx.x * 128;
    const int NT = K / HKT;

    const int l_row = tid >> 1;            // 0..127
    const int l_c = tid & 1;               // chunks c, c+2
    const __half* Ag = A + (m0 + l_row) * (size_t)K;
    const __half* Bg = Bt + (size_t)(n0 + l_row) * K;
    const uint32_t sb = (uint32_t)__cvta_generic_to_shared(hsm);

#define H_ISSUE(kt)                                                             \
    do {                                                                        \
        int s_ = (kt) & (HSTAGES - 1);                                          \
        uint32_t as_ = sb + (s_ * HSTAGE_H + l_row * HROW) * 2;                 \
        uint32_t bs_ = as_ + HA_H * 2;                                          \
        const __half* ag_ = Ag + (kt)*HKT;                                      \
        const __half* bg_ = Bg + (kt)*HKT;                                      \
        cp16(as_ + l_c * 16, ag_ + l_c * 8);                                    \
        cp16(as_ + (l_c + 2) * 16, ag_ + (l_c + 2) * 8);                        \
        cp16(bs_ + l_c * 16, bg_ + l_c * 8);                                    \
        cp16(bs_ + (l_c + 2) * 16, bg_ + (l_c + 2) * 8);                        \
    } while (0)

    H_ISSUE(0);
    asm volatile("cp.async.commit_group;\n");
    H_ISSUE(1);
    asm volatile("cp.async.commit_group;\n");
    H_ISSUE(2);
    asm volatile("cp.async.commit_group;\n");

    float acc[4][4][4];
#pragma unroll
    for (int i = 0; i < 4; i++)
#pragma unroll
        for (int j = 0; j < 4; j++)
#pragma unroll
            for (int r = 0; r < 4; r++) acc[i][j][r] = 0.f;

    for (int kt = 0; kt < NT; kt++) {
        asm volatile("cp.async.wait_group %0;\n" ::"n"(2));
        __syncthreads();

        if (kt + 3 < NT) H_ISSUE(kt + 3);
        asm volatile("cp.async.commit_group;\n");

        const __half* As = hsm + (kt & (HSTAGES - 1)) * HSTAGE_H;
        const __half* Bs = As + HA_H;

#pragma unroll
        for (int s16 = 0; s16 < 32; s16 += 16) {
            uint32_t af[4][4], bf[4][2];
#pragma unroll
            for (int i = 0; i < 4; i++) {
                int row = wm * 64 + i * 16;
                af[i][0] = *(const uint32_t*)&As[(row + g) * HROW + s16 + 2 * t];
                af[i][1] = *(const uint32_t*)&As[(row + g + 8) * HROW + s16 + 2 * t];
                af[i][2] = *(const uint32_t*)&As[(row + g) * HROW + s16 + 2 * t + 8];
                af[i][3] = *(const uint32_t*)&As[(row + g + 8) * HROW + s16 + 2 * t + 8];
            }
#pragma unroll
            for (int j = 0; j < 4; j++) {
                int col = wn * 32 + j * 8 + g;
                bf[j][0] = *(const uint32_t*)&Bs[col * HROW + s16 + 2 * t];
                bf[j][1] = *(const uint32_t*)&Bs[col * HROW + s16 + 2 * t + 8];
            }
#pragma unroll
            for (int i = 0; i < 4; i++)
#pragma unroll
                for (int j = 0; j < 4; j++) {
                    asm volatile(
                        "mma.sync.aligned.m16n8k16.row.col.f32.f16.f16.f32 "
                        "{%0,%1,%2,%3}, {%4,%5,%6,%7}, {%8,%9}, {%0,%1,%2,%3};"
                        : "+f"(acc[i][j][0]), "+f"(acc[i][j][1]),
                          "+f"(acc[i][j][2]), "+f"(acc[i][j][3])
                        : "r"(af[i][0]), "r"(af[i][1]), "r"(af[i][2]), "r"(af[i][3]),
                          "r"(bf[j][0]), "r"(bf[j][1]));
                }
        }
    }

#pragma unroll
    for (int i = 0; i < 4; i++)
#pragma unroll
        for (int j = 0; j < 4; j++) {
            size_t row = m0 + wm * 64 + i * 16 + g;
            int col = n0 + wn * 32 + j * 8 + 2 * t;
            if (HALF_OUT) {
                __half* C = (__half*)Cm;
                *(__half2*)(C + row * N + col) =
                    __floats2half2_rn(acc[i][j][0], acc[i][j][1]);
                *(__half2*)(C + (row + 8) * N + col) =
                    __floats2half2_rn(acc[i][j][2], acc[i][j][3]);
            } else {
                float* C = (float*)Cm;
                *(float2*)(C + row * N + col) = make_float2(acc[i][j][0], acc[i][j][1]);
                *(float2*)(C + (row + 8) * N + col) =
                    make_float2(acc[i][j][2], acc[i][j][3]);
            }
        }
#undef H_ISSUE
}

// ---------------------------------------------------------------------------
// prep16: RoPE on half qkv + reorganize. q/k: [b,h,t,d] (q scaled 0.125);
// v transposed -> [b,h,d,t].
// ---------------------------------------------------------------------------
#define QS_H 72

__global__ __launch_bounds__(256) void prep16(const __half* __restrict__ qkv,
                                              const float* __restrict__ tab,
                                              __half* __restrict__ q16,
                                              __half* __restrict__ k16,
                                              __half* __restrict__ v16t) {
    __shared__ __half vts[64 * QS_H];
    const int tt = blockIdx.x, bh = blockIdx.y;
    const int b = bh >> 4, h = bh & 15;
    const int t0 = tt * 64;
    const int tid = threadIdx.x;

#pragma unroll
    for (int p = 0; p < 8; p++) {
        int idx = tid + p * 256;
        int tl = idx >> 5, i = idx & 31;
        const __half* base =
            qkv + ((size_t)(b * Tt + t0 + tl)) * 3072 + h * 64 + 2 * i;
        float2 cs = *(const float2*)(tab + (t0 + tl) * 64 + 2 * i);
        float2 q = __half22float2(*(const __half2*)(base));
        float2 k = __half22float2(*(const __half2*)(base + 1024));
        __half2 v = *(const __half2*)(base + 2048);
        float qr0 = (q.x * cs.x - q.y * cs.y) * 0.125f;
        float qr1 = (q.y * cs.x + q.x * cs.y) * 0.125f;
        float kr0 = k.x * cs.x - k.y * cs.y;
        float kr1 = k.y * cs.x + k.x * cs.y;
        size_t o = ((size_t)bh * Tt + t0 + tl) * 32 + i;
        ((__half2*)q16)[o] = __floats2half2_rn(qr0, qr1);
        ((__half2*)k16)[o] = __floats2half2_rn(kr0, kr1);
        vts[(2 * i) * QS_H + tl] = __low2half(v);
        vts[(2 * i + 1) * QS_H + tl] = __high2half(v);
    }
    __syncthreads();
    const int d = tid >> 2, seg = tid & 3;
    float4 v0 = *(const float4*)&vts[d * QS_H + seg * 16];
    float4 v1 = *(const float4*)&vts[d * QS_H + seg * 16 + 8];
    __half* dst = v16t + ((size_t)bh * 64 + d) * Tt + t0 + seg * 16;
    *(float4*)dst = v0;
    *(float4*)(dst + 8) = v1;
}

// ---------------------------------------------------------------------------
// flash16: fp16 tensor-core causal flash attention (unchanged logic; epilogue
// now writes half att16 for the fp16 out-proj GEMM).
// ---------------------------------------------------------------------------
#define FL_SMEM ((9216 + 2 * 9216) * 2)

__global__ __launch_bounds__(256, 2) void flash16(const __half* __restrict__ q16,
                                                  const __half* __restrict__ k16,
                                                  const __half* __restrict__ v16t,
                                                  __half* __restrict__ att) {
    extern __shared__ __half hs[];
    const int iq = gridDim.x - 1 - blockIdx.x;
    const int bh = blockIdx.y;
    const int b = bh >> 4, h = bh & 15;
    const int tid = threadIdx.x;
    const int w = tid >> 5, lane = tid & 31;
    const int g = lane >> 2, t = lane & 3;
    const int wr = w * 16;
    const size_t tbase = (size_t)bh * Tt;
    const uint32_t sb = (uint32_t)__cvta_generic_to_shared(hs);
    const int jmax = 2 * iq + 1;

#define ISSUE_KV(jt, s)                                                          \
    do {                                                                         \
        int row_ = tid >> 2;                                                     \
        int cb_ = tid & 3;                                                       \
        const __half* gk_ = k16 + (tbase + (jt)*64 + row_) * 64;                 \
        const __half* gv_ = v16t + ((size_t)bh * 64 + row_) * Tt + (jt)*64;      \
        uint32_t sk_ = sb + (9216 + (s)*9216 + row_ * QS_H) * 2;                 \
        uint32_t sv_ = sk_ + 4608 * 2;                                           \
        cp16(sk_ + cb_ * 16, gk_ + cb_ * 8);                                     \
        cp16(sk_ + (cb_ + 4) * 16, gk_ + (cb_ + 4) * 8);                         \
        cp16(sv_ + cb_ * 16, gv_ + cb_ * 8);                                     \
        cp16(sv_ + (cb_ + 4) * 16, gv_ + (cb_ + 4) * 8);                         \
    } while (0)

    {
        int row = tid >> 1;
        int cb = tid & 1;
        const __half* gq = q16 + (tbase + iq * 128 + row) * 64;
        uint32_t sq = sb + (row * QS_H) * 2;
#pragma unroll
        for (int c = cb; c < 8; c += 2) cp16(sq + c * 16, gq + c * 8);
    }
    ISSUE_KV(0, 0);
    asm volatile("cp.async.commit_group;\n");

    float oacc[8][4];
    float m0 = -1e30f, m1 = -1e30f, l0 = 0.f, l1 = 0.f;
#pragma unroll
    for (int ds = 0; ds < 8; ds++)
#pragma unroll
        for (int r = 0; r < 4; r++) oacc[ds][r] = 0.f;

    uint32_t qf[4][4];
    bool qf_loaded = false;

    for (int jt = 0; jt <= jmax; jt++) {
        if (jt + 1 <= jmax) ISSUE_KV(jt + 1, (jt + 1) & 1);
        asm volatile("cp.async.commit_group;\n");
        asm volatile("cp.async.wait_group %0;\n" ::"n"(1));
        __syncthreads();

        if (!qf_loaded) {
            qf_loaded = true;
#pragma unroll
            for (int kc = 0; kc < 4; kc++) {
                qf[kc][0] = *(const uint32_t*)&hs[(wr + g) * QS_H + kc * 16 + 2 * t];
                qf[kc][1] = *(const uint32_t*)&hs[(wr + g + 8) * QS_H + kc * 16 + 2 * t];
                qf[kc][2] = *(const uint32_t*)&hs[(wr + g) * QS_H + kc * 16 + 2 * t + 8];
                qf[kc][3] = *(const uint32_t*)&hs[(wr + g + 8) * QS_H + kc * 16 + 2 * t + 8];
            }
        }

        const __half* Ks = hs + 9216 + (jt & 1) * 9216;
        const __half* Vs = Ks + 4608;

        float sa[8][4];
#pragma unroll
        for (int ns = 0; ns < 8; ns++)
#pragma unroll
            for (int r = 0; r < 4; r++) sa[ns][r] = 0.f;

#pragma unroll
        for (int kc = 0; kc < 4; kc++)
#pragma unroll
            for (int ns = 0; ns < 8; ns++) {
                uint32_t b0 = *(const uint32_t*)&Ks[(ns * 8 + g) * QS_H + kc * 16 + 2 * t];
                uint32_t b1 = *(const uint32_t*)&Ks[(ns * 8 + g) * QS_H + kc * 16 + 2 * t + 8];
                asm volatile(
                    "mma.sync.aligned.m16n8k16.row.col.f32.f16.f16.f32 "
                    "{%0,%1,%2,%3}, {%4,%5,%6,%7}, {%8,%9}, {%0,%1,%2,%3};"
                    : "+f"(sa[ns][0]), "+f"(sa[ns][1]), "+f"(sa[ns][2]), "+f"(sa[ns][3])
                    : "r"(qf[kc][0]), "r"(qf[kc][1]), "r"(qf[kc][2]), "r"(qf[kc][3]),
                      "r"(b0), "r"(b1));
            }

        if (jt >= 2 * iq) {
            const int row0 = iq * 128 + wr + g;
            const int row1 = row0 + 8;
#pragma unroll
            for (int ns = 0; ns < 8; ns++) {
                int c0 = jt * 64 + ns * 8 + 2 * t;
                if (c0 > row0) sa[ns][0] = -1e30f;
                if (c0 + 1 > row0) sa[ns][1] = -1e30f;
                if (c0 > row1) sa[ns][2] = -1e30f;
                if (c0 + 1 > row1) sa[ns][3] = -1e30f;
            }
        }

        {
            float mx0 = -1e30f, mx1 = -1e30f;
#pragma unroll
            for (int ns = 0; ns < 8; ns++) {
                mx0 = fmaxf(mx0, fmaxf(sa[ns][0], sa[ns][1]));
                mx1 = fmaxf(mx1, fmaxf(sa[ns][2], sa[ns][3]));
            }
#pragma unroll
            for (int off = 1; off <= 2; off <<= 1) {
                mx0 = fmaxf(mx0, __shfl_xor_sync(0xffffffffu, mx0, off));
                mx1 = fmaxf(mx1, __shfl_xor_sync(0xffffffffu, mx1, off));
            }
            float mn0 = fmaxf(m0, mx0), mn1 = fmaxf(m1, mx1);
            float al0 = __expf(m0 - mn0), al1 = __expf(m1 - mn1);
            float s0 = 0.f, s1 = 0.f;
#pragma unroll
            for (int ns = 0; ns < 8; ns++) {
                sa[ns][0] = __expf(sa[ns][0] - mn0);
                sa[ns][1] = __expf(sa[ns][1] - mn0);
                sa[ns][2] = __expf(sa[ns][2] - mn1);
                sa[ns][3] = __expf(sa[ns][3] - mn1);
                s0 += sa[ns][0] + sa[ns][1];
                s1 += sa[ns][2] + sa[ns][3];
            }
#pragma unroll
            for (int off = 1; off <= 2; off <<= 1) {
                s0 += __shfl_xor_sync(0xffffffffu, s0, off);
                s1 += __shfl_xor_sync(0xffffffffu, s1, off);
            }
            l0 = l0 * al0 + s0;
            l1 = l1 * al1 + s1;
            m0 = mn0;
            m1 = mn1;
#pragma unroll
            for (int ds = 0; ds < 8; ds++) {
                oacc[ds][0] *= al0;
                oacc[ds][1] *= al0;
                oacc[ds][2] *= al1;
                oacc[ds][3] *= al1;
            }
        }

        uint32_t pf[4][4];
#pragma unroll
        for (int kc = 0; kc < 4; kc++) {
            __half2 h0 = __floats2half2_rn(sa[2 * kc][0], sa[2 * kc][1]);
            __half2 h1 = __floats2half2_rn(sa[2 * kc][2], sa[2 * kc][3]);
            __half2 h2 = __floats2half2_rn(sa[2 * kc + 1][0], sa[2 * kc + 1][1]);
            __half2 h3 = __floats2half2_rn(sa[2 * kc + 1][2], sa[2 * kc + 1][3]);
            pf[kc][0] = *(uint32_t*)&h0;
            pf[kc][1] = *(uint32_t*)&h1;
            pf[kc][2] = *(uint32_t*)&h2;
            pf[kc][3] = *(uint32_t*)&h3;
        }

#pragma unroll
        for (int kc = 0; kc < 4; kc++)
#pragma unroll
            for (int ds = 0; ds < 8; ds++) {
                uint32_t b0 = *(const uint32_t*)&Vs[(ds * 8 + g) * QS_H + kc * 16 + 2 * t];
                uint32_t b1 = *(const uint32_t*)&Vs[(ds * 8 + g) * QS_H + kc * 16 + 2 * t + 8];
                asm volatile(
                    "mma.sync.aligned.m16n8k16.row.col.f32.f16.f16.f32 "
                    "{%0,%1,%2,%3}, {%4,%5,%6,%7}, {%8,%9}, {%0,%1,%2,%3};"
                    : "+f"(oacc[ds][0]), "+f"(oacc[ds][1]), "+f"(oacc[ds][2]),
                      "+f"(oacc[ds][3])
                    : "r"(pf[kc][0]), "r"(pf[kc][1]), "r"(pf[kc][2]), "r"(pf[kc][3]),
                      "r"(b0), "r"(b1));
            }

        __syncthreads();
    }

    const float il0 = 1.f / l0, il1 = 1.f / l1;
    __half* p0 = att + ((size_t)b * Tt + iq * 128 + wr + g) * Cc + h * 64;
    __half* p1 = p0 + 8 * (size_t)Cc;
#pragma unroll
    for (int ds = 0; ds < 8; ds++) {
        *(__half2*)(p0 + ds * 8 + 2 * t) =
            __floats2half2_rn(oacc[ds][0] * il0, oacc[ds][1] * il0);
        *(__half2*)(p1 + ds * 8 + 2 * t) =
            __floats2half2_rn(oacc[ds][2] * il1, oacc[ds][3] * il1);
    }
#undef ISSUE_KV
}

// ---------------------------------------------------------------------------
extern "C" void kernel_launch(void* const* d_in, const int* in_sizes, int n_in,
                              void* d_out, int out_size) {
    const float* x = (const float*)d_in[0];
    const float* Wqkv = (const float*)d_in[1];
    const float* Wout = (const float*)d_in[2];
    float* out = (float*)d_out;

    __half *x16, *wqkvT, *woutT, *qkv16, *qh, *kh, *vt, *att16;
    float* rope;
    cudaGetSymbolAddress((void**)&x16, g_x16);
    cudaGetSymbolAddress((void**)&wqkvT, g_wqkvT);
    cudaGetSymbolAddress((void**)&woutT, g_woutT);
    cudaGetSymbolAddress((void**)&qkv16, g_qkv16);
    cudaGetSymbolAddress((void**)&qh, g_qh);
    cudaGetSymbolAddress((void**)&kh, g_kh);
    cudaGetSymbolAddress((void**)&vt, g_vt);
    cudaGetSymbolAddress((void**)&att16, g_att16);
    cudaGetSymbolAddress((void**)&rope, g_rope);

    cudaFuncSetAttribute(hgemm<true>, cudaFuncAttributeMaxDynamicSharedMemorySize,
                         HGEMM_SMEM);
    cudaFuncSetAttribute(hgemm<false>, cudaFuncAttributeMaxDynamicSharedMemorySize,
                         HGEMM_SMEM);
    cudaFuncSetAttribute(flash16, cudaFuncAttributeMaxDynamicSharedMemorySize,
                         FL_SMEM);

    // 0) conversions + rope table
    f32_to_f16<<<(BTC / 4 + 255) / 256, 256>>>(x, x16, BTC / 4);
    transpose_to_half<<<dim3(3 * Cc / 32, Cc / 32), dim3(32, 8)>>>(Wqkv, wqkvT,
                                                                   Cc, 3 * Cc);
    transpose_to_half<<<dim3(Cc / 32, Cc / 32), dim3(32, 8)>>>(Wout, woutT, Cc, Cc);
    rope_table_k<<<Tt * 32 / 256, 256>>>(rope);

    // 1) qkv16 = x16 @ WqkvT^T   (fp16 tensor cores, half out)
    hgemm<true><<<dim3(3072 / 128, 8192 / 128), 256, HGEMM_SMEM>>>(x16, wqkvT,
                                                                   qkv16, 3072, 1024);
    // 2) RoPE + layout (q scaled, v transposed)
    prep16<<<dim3(Tt / 64, Bb * Hh), 256>>>(qkv16, rope, qh, kh, vt);
    // 3) fp16 tensor-core causal flash attention -> att16 (half)
    flash16<<<dim3(Tt / 128, Bb * Hh), 256, FL_SMEM>>>(qh, kh, vt, att16);
    // 4) out = att16 @ WoutT^T   (fp16 tensor cores, fp32 out)
    hgemm<false><<<dim3(1024 / 128, 8192 / 128), 256, HGEMM_SMEM>>>(att16, woutT,
                                                                    out, 1024, 1024);
}

// round 11
// speedup vs baseline: 5.5302x; 1.1019x over previous
#include <cuda_runtime.h>
#include <cuda_fp16.h>
#include <math.h>
#include <stdint.h>

#define Bb 4
#define Tt 2048
#define Cc 1024
#define Hh 16
#define Dd 64
#define BTC (Bb * Tt * Cc)

// Scratch (no cudaMalloc allowed) — all-half dataflow
__device__ __half g_x16[BTC];
__device__ __half g_wqkvT[3 * Cc * Cc];
__device__ __half g_woutT[Cc * Cc];
__device__ __half g_qkv16[3 * BTC];
__device__ __half g_qh[BTC];
__device__ __half g_kh[BTC];
__device__ __half g_vt[BTC];
__device__ __half g_att16[BTC];
__device__ float g_rope[Tt * 64];

__device__ __forceinline__ void cp16(uint32_t saddr, const void* gaddr) {
    asm volatile("cp.async.cg.shared.global [%0], [%1], 16;\n" ::"r"(saddr), "l"(gaddr));
}

#define LDSM_X4(r0, r1, r2, r3, addr)                                          \
    asm volatile("ldmatrix.sync.aligned.m8n8.x4.shared.b16 {%0,%1,%2,%3}, [%4];" \
                 : "=r"(r0), "=r"(r1), "=r"(r2), "=r"(r3)                       \
                 : "r"(addr))

// ---------------------------------------------------------------------------
__global__ __launch_bounds__(256) void f32_to_f16(const float* __restrict__ in,
                                                  __half* __restrict__ out, int n4) {
    int i = blockIdx.x * blockDim.x + threadIdx.x;
    if (i < n4) {
        float4 v = ((const float4*)in)[i];
        ((__half2*)out)[2 * i] = __floats2half2_rn(v.x, v.y);
        ((__half2*)out)[2 * i + 1] = __floats2half2_rn(v.z, v.w);
    }
}

// ---------------------------------------------------------------------------
__global__ __launch_bounds__(256) void transpose_to_half(const float* __restrict__ in,
                                                         __half* __restrict__ out,
                                                         int K, int N) {
    __shared__ float tile[32][33];
    int k0 = blockIdx.y * 32, n0 = blockIdx.x * 32;
#pragma unroll
    for (int r = 0; r < 4; r++) {
        int k = threadIdx.y + r * 8;
        tile[k][threadIdx.x] = in[(size_t)(k0 + k) * N + n0 + threadIdx.x];
    }
    __syncthreads();
#pragma unroll
    for (int r = 0; r < 4; r++) {
        int n = threadIdx.y + r * 8;
        out[(size_t)(n0 + n) * K + k0 + threadIdx.x] =
            __float2half_rn(tile[threadIdx.x][n]);
    }
}

// ---------------------------------------------------------------------------
// RoPE table: double only for freq + range reduction, float trig.
// ---------------------------------------------------------------------------
__global__ __launch_bounds__(256) void rope_table_k(float* __restrict__ tab) {
    int idx = blockIdx.x * 256 + threadIdx.x;
    int t = idx >> 5, i = idx & 31;
    double invf = exp2(-(double)i * (13.287712379549449 / 32.0)); // 10000^(-i/32)
    double a = (double)t * invf;
    double r = a - rint(a * 0.15915494309189535) * 6.283185307179586;
    float s, c;
    sincosf((float)r, &s, &c);
    tab[t * 64 + 2 * i] = c;
    tab[t * 64 + 2 * i + 1] = s;
}

// ---------------------------------------------------------------------------
// fp16 GEMM with ldmatrix fragment loads.
// ---------------------------------------------------------------------------
#define HSTAGES 4
#define HKT 32
#define HROW 40
#define HA_H (128 * HROW)
#define HSTAGE_H (2 * HA_H)
#define HGEMM_SMEM (HSTAGES * HSTAGE_H * 2)

template <bool HALF_OUT>
__global__ __launch_bounds__(256, 2) void hgemm(const __half* __restrict__ A,
                                                const __half* __restrict__ Bt,
                                                void* __restrict__ Cm,
                                                int N, int K) {
    extern __shared__ __half hsm[];
    const int tid = threadIdx.x;
    const int warp = tid >> 5, lane = tid & 31;
    const int wm = warp & 1, wn = warp >> 1;
    const int g = lane >> 2, t = lane & 3;
    const size_t m0 = (size_t)blockIdx.y * 128;
    const int n0 = blockIdx.x * 128;
    const int NT = K / HKT;

    const int l_row = tid >> 1;
    const int l_c = tid & 1;
    const __half* Ag = A + (m0 + l_row) * (size_t)K;
    const __half* Bg = Bt + (size_t)(n0 + l_row) * K;
    const uint32_t sb = (uint32_t)__cvta_generic_to_shared(hsm);

    // LDSM lane addressing (in halves, relative to stage base)
    const int a_off = (lane & 15) * HROW + (lane >> 4) * 8;       // + row0*HROW + s16
    const int b_off = (((lane >> 4) & 1) * 8 + (lane & 7)) * HROW + ((lane >> 3) & 1) * 8;

#define H_ISSUE(kt)                                                             \
    do {                                                                        \
        int s_ = (kt) & (HSTAGES - 1);                                          \
        uint32_t as_ = sb + (s_ * HSTAGE_H + l_row * HROW) * 2;                 \
        uint32_t bs_ = as_ + HA_H * 2;                                          \
        const __half* ag_ = Ag + (kt)*HKT;                                      \
        const __half* bg_ = Bg + (kt)*HKT;                                      \
        cp16(as_ + l_c * 16, ag_ + l_c * 8);                                    \
        cp16(as_ + (l_c + 2) * 16, ag_ + (l_c + 2) * 8);                        \
        cp16(bs_ + l_c * 16, bg_ + l_c * 8);                                    \
        cp16(bs_ + (l_c + 2) * 16, bg_ + (l_c + 2) * 8);                        \
    } while (0)

    H_ISSUE(0);
    asm volatile("cp.async.commit_group;\n");
    H_ISSUE(1);
    asm volatile("cp.async.commit_group;\n");
    H_ISSUE(2);
    asm volatile("cp.async.commit_group;\n");

    float acc[4][4][4];
#pragma unroll
    for (int i = 0; i < 4; i++)
#pragma unroll
        for (int j = 0; j < 4; j++)
#pragma unroll
            for (int r = 0; r < 4; r++) acc[i][j][r] = 0.f;

    for (int kt = 0; kt < NT; kt++) {
        asm volatile("cp.async.wait_group %0;\n" ::"n"(2));
        __syncthreads();

        if (kt + 3 < NT) H_ISSUE(kt + 3);
        asm volatile("cp.async.commit_group;\n");

        const uint32_t As = sb + ((kt & (HSTAGES - 1)) * HSTAGE_H) * 2;
        const uint32_t Bs = As + HA_H * 2;

#pragma unroll
        for (int s16 = 0; s16 < 32; s16 += 16) {
            uint32_t af[4][4], bf[4][2];
#pragma unroll
            for (int i = 0; i < 4; i++) {
                uint32_t addr = As + ((wm * 64 + i * 16) * HROW + s16 + a_off) * 2;
                LDSM_X4(af[i][0], af[i][1], af[i][2], af[i][3], addr);
            }
#pragma unroll
            for (int jp = 0; jp < 2; jp++) {
                uint32_t addr = Bs + ((wn * 32 + jp * 16) * HROW + s16 + b_off) * 2;
                LDSM_X4(bf[2 * jp][0], bf[2 * jp][1], bf[2 * jp + 1][0],
                        bf[2 * jp + 1][1], addr);
            }
#pragma unroll
            for (int i = 0; i < 4; i++)
#pragma unroll
                for (int j = 0; j < 4; j++) {
                    asm volatile(
                        "mma.sync.aligned.m16n8k16.row.col.f32.f16.f16.f32 "
                        "{%0,%1,%2,%3}, {%4,%5,%6,%7}, {%8,%9}, {%0,%1,%2,%3};"
                        : "+f"(acc[i][j][0]), "+f"(acc[i][j][1]),
                          "+f"(acc[i][j][2]), "+f"(acc[i][j][3])
                        : "r"(af[i][0]), "r"(af[i][1]), "r"(af[i][2]), "r"(af[i][3]),
                          "r"(bf[j][0]), "r"(bf[j][1]));
                }
        }
    }

#pragma unroll
    for (int i = 0; i < 4; i++)
#pragma unroll
        for (int j = 0; j < 4; j++) {
            size_t row = m0 + wm * 64 + i * 16 + g;
            int col = n0 + wn * 32 + j * 8 + 2 * t;
            if (HALF_OUT) {
                __half* C = (__half*)Cm;
                *(__half2*)(C + row * N + col) =
                    __floats2half2_rn(acc[i][j][0], acc[i][j][1]);
                *(__half2*)(C + (row + 8) * N + col) =
                    __floats2half2_rn(acc[i][j][2], acc[i][j][3]);
            } else {
                float* C = (float*)Cm;
                *(float2*)(C + row * N + col) = make_float2(acc[i][j][0], acc[i][j][1]);
                *(float2*)(C + (row + 8) * N + col) =
                    make_float2(acc[i][j][2], acc[i][j][3]);
            }
        }
#undef H_ISSUE
}

// ---------------------------------------------------------------------------
// prep16 (unchanged from R9)
// ---------------------------------------------------------------------------
#define QS_H 72

__global__ __launch_bounds__(256) void prep16(const __half* __restrict__ qkv,
                                              const float* __restrict__ tab,
                                              __half* __restrict__ q16,
                                              __half* __restrict__ k16,
                                              __half* __restrict__ v16t) {
    __shared__ __half vts[64 * QS_H];
    const int tt = blockIdx.x, bh = blockIdx.y;
    const int b = bh >> 4, h = bh & 15;
    const int t0 = tt * 64;
    const int tid = threadIdx.x;

#pragma unroll
    for (int p = 0; p < 8; p++) {
        int idx = tid + p * 256;
        int tl = idx >> 5, i = idx & 31;
        const __half* base =
            qkv + ((size_t)(b * Tt + t0 + tl)) * 3072 + h * 64 + 2 * i;
        float2 cs = *(const float2*)(tab + (t0 + tl) * 64 + 2 * i);
        float2 q = __half22float2(*(const __half2*)(base));
        float2 k = __half22float2(*(const __half2*)(base + 1024));
        __half2 v = *(const __half2*)(base + 2048);
        float qr0 = (q.x * cs.x - q.y * cs.y) * 0.125f;
        float qr1 = (q.y * cs.x + q.x * cs.y) * 0.125f;
        float kr0 = k.x * cs.x - k.y * cs.y;
        float kr1 = k.y * cs.x + k.x * cs.y;
        size_t o = ((size_t)bh * Tt + t0 + tl) * 32 + i;
        ((__half2*)q16)[o] = __floats2half2_rn(qr0, qr1);
        ((__half2*)k16)[o] = __floats2half2_rn(kr0, kr1);
        vts[(2 * i) * QS_H + tl] = __low2half(v);
        vts[(2 * i + 1) * QS_H + tl] = __high2half(v);
    }
    __syncthreads();
    const int d = tid >> 2, seg = tid & 3;
    float4 v0 = *(const float4*)&vts[d * QS_H + seg * 16];
    float4 v1 = *(const float4*)&vts[d * QS_H + seg * 16 + 8];
    __half* dst = v16t + ((size_t)bh * 64 + d) * Tt + t0 + seg * 16;
    *(float4*)dst = v0;
    *(float4*)(dst + 8) = v1;
}

// ---------------------------------------------------------------------------
// flash16 with ldmatrix K/V/Q fragment loads.
// ---------------------------------------------------------------------------
#define FL_SMEM ((9216 + 2 * 9216) * 2)

__global__ __launch_bounds__(256, 2) void flash16(const __half* __restrict__ q16,
                                                  const __half* __restrict__ k16,
                                                  const __half* __restrict__ v16t,
                                                  __half* __restrict__ att) {
    extern __shared__ __half hs[];
    const int iq = gridDim.x - 1 - blockIdx.x;
    const int bh = blockIdx.y;
    const int b = bh >> 4, h = bh & 15;
    const int tid = threadIdx.x;
    const int w = tid >> 5, lane = tid & 31;
    const int g = lane >> 2, t = lane & 3;
    const int wr = w * 16;
    const size_t tbase = (size_t)bh * Tt;
    const uint32_t sb = (uint32_t)__cvta_generic_to_shared(hs);
    const int jmax = 2 * iq + 1;

    // LDSM lane offsets (halves)
    const int a_off = (lane & 15) * QS_H + (lane >> 4) * 8;                    // Q (A-pattern)
    const int b_off = (((lane >> 4) & 1) * 8 + (lane & 7)) * QS_H + ((lane >> 3) & 1) * 8;  // K/V (B-pattern)

#define ISSUE_KV(jt, s)                                                          \
    do {                                                                         \
        int row_ = tid >> 2;                                                     \
        int cb_ = tid & 3;                                                       \
        const __half* gk_ = k16 + (tbase + (jt)*64 + row_) * 64;                 \
        const __half* gv_ = v16t + ((size_t)bh * 64 + row_) * Tt + (jt)*64;      \
        uint32_t sk_ = sb + (9216 + (s)*9216 + row_ * QS_H) * 2;                 \
        uint32_t sv_ = sk_ + 4608 * 2;                                           \
        cp16(sk_ + cb_ * 16, gk_ + cb_ * 8);                                     \
        cp16(sk_ + (cb_ + 4) * 16, gk_ + (cb_ + 4) * 8);                         \
        cp16(sv_ + cb_ * 16, gv_ + cb_ * 8);                                     \
        cp16(sv_ + (cb_ + 4) * 16, gv_ + (cb_ + 4) * 8);                         \
    } while (0)

    {
        int row = tid >> 1;
        int cb = tid & 1;
        const __half* gq = q16 + (tbase + iq * 128 + row) * 64;
        uint32_t sq = sb + (row * QS_H) * 2;
#pragma unroll
        for (int c = cb; c < 8; c += 2) cp16(sq + c * 16, gq + c * 8);
    }
    ISSUE_KV(0, 0);
    asm volatile("cp.async.commit_group;\n");

    float oacc[8][4];
    float m0 = -1e30f, m1 = -1e30f, l0 = 0.f, l1 = 0.f;
#pragma unroll
    for (int ds = 0; ds < 8; ds++)
#pragma unroll
        for (int r = 0; r < 4; r++) oacc[ds][r] = 0.f;

    uint32_t qf[4][4];
    bool qf_loaded = false;

    for (int jt = 0; jt <= jmax; jt++) {
        if (jt + 1 <= jmax) ISSUE_KV(jt + 1, (jt + 1) & 1);
        asm volatile("cp.async.commit_group;\n");
        asm volatile("cp.async.wait_group %0;\n" ::"n"(1));
        __syncthreads();

        if (!qf_loaded) {
            qf_loaded = true;
#pragma unroll
            for (int kc = 0; kc < 4; kc++) {
                uint32_t addr = sb + (wr * QS_H + kc * 16 + a_off) * 2;
                LDSM_X4(qf[kc][0], qf[kc][1], qf[kc][2], qf[kc][3], addr);
            }
        }

        const uint32_t Ks = sb + (9216 + (jt & 1) * 9216) * 2;
        const uint32_t Vs = Ks + 4608 * 2;

        // S = Q @ K^T
        float sa[8][4];
#pragma unroll
        for (int ns = 0; ns < 8; ns++)
#pragma unroll
            for (int r = 0; r < 4; r++) sa[ns][r] = 0.f;

#pragma unroll
        for (int kc = 0; kc < 4; kc++)
#pragma unroll
            for (int ns2 = 0; ns2 < 4; ns2++) {
                uint32_t kb0, kb1, kb2, kb3;
                uint32_t addr = Ks + (ns2 * 16 * QS_H + kc * 16 + b_off) * 2;
                LDSM_X4(kb0, kb1, kb2, kb3, addr);
                asm volatile(
                    "mma.sync.aligned.m16n8k16.row.col.f32.f16.f16.f32 "
                    "{%0,%1,%2,%3}, {%4,%5,%6,%7}, {%8,%9}, {%0,%1,%2,%3};"
                    : "+f"(sa[2 * ns2][0]), "+f"(sa[2 * ns2][1]),
                      "+f"(sa[2 * ns2][2]), "+f"(sa[2 * ns2][3])
                    : "r"(qf[kc][0]), "r"(qf[kc][1]), "r"(qf[kc][2]), "r"(qf[kc][3]),
                      "r"(kb0), "r"(kb1));
                asm volatile(
                    "mma.sync.aligned.m16n8k16.row.col.f32.f16.f16.f32 "
                    "{%0,%1,%2,%3}, {%4,%5,%6,%7}, {%8,%9}, {%0,%1,%2,%3};"
                    : "+f"(sa[2 * ns2 + 1][0]), "+f"(sa[2 * ns2 + 1][1]),
                      "+f"(sa[2 * ns2 + 1][2]), "+f"(sa[2 * ns2 + 1][3])
                    : "r"(qf[kc][0]), "r"(qf[kc][1]), "r"(qf[kc][2]), "r"(qf[kc][3]),
                      "r"(kb2), "r"(kb3));
            }

        if (jt >= 2 * iq) {
            const int row0 = iq * 128 + wr + g;
            const int row1 = row0 + 8;
#pragma unroll
            for (int ns = 0; ns < 8; ns++) {
                int c0 = jt * 64 + ns * 8 + 2 * t;
                if (c0 > row0) sa[ns][0] = -1e30f;
                if (c0 + 1 > row0) sa[ns][1] = -1e30f;
                if (c0 > row1) sa[ns][2] = -1e30f;
                if (c0 + 1 > row1) sa[ns][3] = -1e30f;
            }
        }

        {
            float mx0 = -1e30f, mx1 = -1e30f;
#pragma unroll
            for (int ns = 0; ns < 8; ns++) {
                mx0 = fmaxf(mx0, fmaxf(sa[ns][0], sa[ns][1]));
                mx1 = fmaxf(mx1, fmaxf(sa[ns][2], sa[ns][3]));
            }
#pragma unroll
            for (int off = 1; off <= 2; off <<= 1) {
                mx0 = fmaxf(mx0, __shfl_xor_sync(0xffffffffu, mx0, off));
                mx1 = fmaxf(mx1, __shfl_xor_sync(0xffffffffu, mx1, off));
            }
            float mn0 = fmaxf(m0, mx0), mn1 = fmaxf(m1, mx1);
            float al0 = __expf(m0 - mn0), al1 = __expf(m1 - mn1);
            float s0 = 0.f, s1 = 0.f;
#pragma unroll
            for (int ns = 0; ns < 8; ns++) {
                sa[ns][0] = __expf(sa[ns][0] - mn0);
                sa[ns][1] = __expf(sa[ns][1] - mn0);
                sa[ns][2] = __expf(sa[ns][2] - mn1);
                sa[ns][3] = __expf(sa[ns][3] - mn1);
                s0 += sa[ns][0] + sa[ns][1];
                s1 += sa[ns][2] + sa[ns][3];
            }
#pragma unroll
            for (int off = 1; off <= 2; off <<= 1) {
                s0 += __shfl_xor_sync(0xffffffffu, s0, off);
                s1 += __shfl_xor_sync(0xffffffffu, s1, off);
            }
            l0 = l0 * al0 + s0;
            l1 = l1 * al1 + s1;
            m0 = mn0;
            m1 = mn1;
#pragma unroll
            for (int ds = 0; ds < 8; ds++) {
                oacc[ds][0] *= al0;
                oacc[ds][1] *= al0;
                oacc[ds][2] *= al1;
                oacc[ds][3] *= al1;
            }
        }

        uint32_t pf[4][4];
#pragma unroll
        for (int kc = 0; kc < 4; kc++) {
            __half2 h0 = __floats2half2_rn(sa[2 * kc][0], sa[2 * kc][1]);
            __half2 h1 = __floats2half2_rn(sa[2 * kc][2], sa[2 * kc][3]);
            __half2 h2 = __floats2half2_rn(sa[2 * kc + 1][0], sa[2 * kc + 1][1]);
            __half2 h3 = __floats2half2_rn(sa[2 * kc + 1][2], sa[2 * kc + 1][3]);
            pf[kc][0] = *(uint32_t*)&h0;
            pf[kc][1] = *(uint32_t*)&h1;
            pf[kc][2] = *(uint32_t*)&h2;
            pf[kc][3] = *(uint32_t*)&h3;
        }

        // O += P @ V (V transposed in smem: rows = d)
#pragma unroll
        for (int kc = 0; kc < 4; kc++)
#pragma unroll
            for (int ds2 = 0; ds2 < 4; ds2++) {
                uint32_t vb0, vb1, vb2, vb3;
                uint32_t addr = Vs + (ds2 * 16 * QS_H + kc * 16 + b_off) * 2;
                LDSM_X4(vb0, vb1, vb2, vb3, addr);
                asm volatile(
                    "mma.sync.aligned.m16n8k16.row.col.f32.f16.f16.f32 "
                    "{%0,%1,%2,%3}, {%4,%5,%6,%7}, {%8,%9}, {%0,%1,%2,%3};"
                    : "+f"(oacc[2 * ds2][0]), "+f"(oacc[2 * ds2][1]),
                      "+f"(oacc[2 * ds2][2]), "+f"(oacc[2 * ds2][3])
                    : "r"(pf[kc][0]), "r"(pf[kc][1]), "r"(pf[kc][2]), "r"(pf[kc][3]),
                      "r"(vb0), "r"(vb1));
                asm volatile(
                    "mma.sync.aligned.m16n8k16.row.col.f32.f16.f16.f32 "
                    "{%0,%1,%2,%3}, {%4,%5,%6,%7}, {%8,%9}, {%0,%1,%2,%3};"
                    : "+f"(oacc[2 * ds2 + 1][0]), "+f"(oacc[2 * ds2 + 1][1]),
                      "+f"(oacc[2 * ds2 + 1][2]), "+f"(oacc[2 * ds2 + 1][3])
                    : "r"(pf[kc][0]), "r"(pf[kc][1]), "r"(pf[kc][2]), "r"(pf[kc][3]),
                      "r"(vb2), "r"(vb3));
            }

        __syncthreads();
    }

    const float il0 = 1.f / l0, il1 = 1.f / l1;
    __half* p0 = att + ((size_t)b * Tt + iq * 128 + wr + g) * Cc + h * 64;
    __half* p1 = p0 + 8 * (size_t)Cc;
#pragma unroll
    for (int ds = 0; ds < 8; ds++) {
        *(__half2*)(p0 + ds * 8 + 2 * t) =
            __floats2half2_rn(oacc[ds][0] * il0, oacc[ds][1] * il0);
        *(__half2*)(p1 + ds * 8 + 2 * t) =
            __floats2half2_rn(oacc[ds][2] * il1, oacc[ds][3] * il1);
    }
#undef ISSUE_KV
}

// ---------------------------------------------------------------------------
extern "C" void kernel_launch(void* const* d_in, const int* in_sizes, int n_in,
                              void* d_out, int out_size) {
    const float* x = (const float*)d_in[0];
    const float* Wqkv = (const float*)d_in[1];
    const float* Wout = (const float*)d_in[2];
    float* out = (float*)d_out;

    __half *x16, *wqkvT, *woutT, *qkv16, *qh, *kh, *vt, *att16;
    float* rope;
    cudaGetSymbolAddress((void**)&x16, g_x16);
    cudaGetSymbolAddress((void**)&wqkvT, g_wqkvT);
    cudaGetSymbolAddress((void**)&woutT, g_woutT);
    cudaGetSymbolAddress((void**)&qkv16, g_qkv16);
    cudaGetSymbolAddress((void**)&qh, g_qh);
    cudaGetSymbolAddress((void**)&kh, g_kh);
    cudaGetSymbolAddress((void**)&vt, g_vt);
    cudaGetSymbolAddress((void**)&att16, g_att16);
    cudaGetSymbolAddress((void**)&rope, g_rope);

    cudaFuncSetAttribute(hgemm<true>, cudaFuncAttributeMaxDynamicSharedMemorySize,
                         HGEMM_SMEM);
    cudaFuncSetAttribute(hgemm<false>, cudaFuncAttributeMaxDynamicSharedMemorySize,
                         HGEMM_SMEM);
    cudaFuncSetAttribute(flash16, cudaFuncAttributeMaxDynamicSharedMemorySize,
                         FL_SMEM);

    f32_to_f16<<<(BTC / 4 + 255) / 256, 256>>>(x, x16, BTC / 4);
    transpose_to_half<<<dim3(3 * Cc / 32, Cc / 32), dim3(32, 8)>>>(Wqkv, wqkvT,
                                                                   Cc, 3 * Cc);
    transpose_to_half<<<dim3(Cc / 32, Cc / 32), dim3(32, 8)>>>(Wout, woutT, Cc, Cc);
    rope_table_k<<<Tt * 32 / 256, 256>>>(rope);

    hgemm<true><<<dim3(3072 / 128, 8192 / 128), 256, HGEMM_SMEM>>>(x16, wqkvT,
                                                                   qkv16, 3072, 1024);
    prep16<<<dim3(Tt / 64, Bb * Hh), 256>>>(qkv16, rope, qh, kh, vt);
    flash16<<<dim3(Tt / 128, Bb * Hh), 256, FL_SMEM>>>(qh, kh, vt, att16);
    hgemm<false><<<dim3(1024 / 128, 8192 / 128), 256, HGEMM_SMEM>>>(att16, woutT,
                                                                    out, 1024, 1024);
}

// round 14
// speedup vs baseline: 5.6413x; 1.0201x over previous
#include <cuda_runtime.h>
#include <cuda_fp16.h>
#include <math.h>
#include <stdint.h>

#define Bb 4
#define Tt 2048
#define Cc 1024
#define Hh 16
#define Dd 64
#define BTC (Bb * Tt * Cc)

// Scratch (no cudaMalloc allowed) — all-half dataflow
__device__ __half g_x16[BTC];
__device__ __half g_wqkvT[3 * Cc * Cc];
__device__ __half g_woutT[Cc * Cc];
__device__ __half g_qh[BTC];   // q roped+scaled  [b,h,t,d]
__device__ __half g_kh[BTC];   // k roped         [b,h,t,d]
__device__ __half g_vt[BTC];   // v transposed    [b,h,d,t]
__device__ __half g_att16[BTC];
__device__ float g_rope[Tt * 64];

__device__ __forceinline__ void cp16(uint32_t saddr, const void* gaddr) {
    asm volatile("cp.async.cg.shared.global [%0], [%1], 16;\n" ::"r"(saddr), "l"(gaddr));
}

#define LDSM_X4(r0, r1, r2, r3, addr)                                            \
    asm volatile("ldmatrix.sync.aligned.m8n8.x4.shared.b16 {%0,%1,%2,%3}, [%4];" \
                 : "=r"(r0), "=r"(r1), "=r"(r2), "=r"(r3)                        \
                 : "r"(addr))

// ---------------------------------------------------------------------------
__global__ __launch_bounds__(256) void f32_to_f16(const float* __restrict__ in,
                                                  __half* __restrict__ out, int n4) {
    int i = blockIdx.x * blockDim.x + threadIdx.x;
    if (i < n4) {
        float4 v = ((const float4*)in)[i];
        ((__half2*)out)[2 * i] = __floats2half2_rn(v.x, v.y);
        ((__half2*)out)[2 * i + 1] = __floats2half2_rn(v.z, v.w);
    }
}

// ---------------------------------------------------------------------------
__global__ __launch_bounds__(256) void transpose_to_half(const float* __restrict__ in,
                                                         __half* __restrict__ out,
                                                         int K, int N) {
    __shared__ float tile[32][33];
    int k0 = blockIdx.y * 32, n0 = blockIdx.x * 32;
#pragma unroll
    for (int r = 0; r < 4; r++) {
        int k = threadIdx.y + r * 8;
        tile[k][threadIdx.x] = in[(size_t)(k0 + k) * N + n0 + threadIdx.x];
    }
    __syncthreads();
#pragma unroll
    for (int r = 0; r < 4; r++) {
        int n = threadIdx.y + r * 8;
        out[(size_t)(n0 + n) * K + k0 + threadIdx.x] =
            __float2half_rn(tile[threadIdx.x][n]);
    }
}

// ---------------------------------------------------------------------------
__global__ __launch_bounds__(256) void rope_table_k(float* __restrict__ tab) {
    int idx = blockIdx.x * 256 + threadIdx.x;
    int t = idx >> 5, i = idx & 31;
    double invf = exp2(-(double)i * (13.287712379549449 / 32.0)); // 10000^(-i/32)
    double a = (double)t * invf;
    double r = a - rint(a * 0.15915494309189535) * 6.283185307179586;
    float s, c;
    sincosf((float)r, &s, &c);
    tab[t * 64 + 2 * i] = c;
    tab[t * 64 + 2 * i + 1] = s;
}

// ---------------------------------------------------------------------------
// fp16 GEMM with ldmatrix fragment loads.
// EPI=0: plain fp32 output to Cm.
// EPI=2: fused qkv epilogue — RoPE on q/k (fp32, pre-rounding), scatter to
//        qh/kh [b,h,t,d] and vt [b,h,d,t]. Section (q/k/v) uniform per CTA.
// ---------------------------------------------------------------------------
#define HSTAGES 4
#define HKT 32
#define HROW 40
#define HA_H (128 * HROW)
#define HSTAGE_H (2 * HA_H)
#define HGEMM_SMEM (HSTAGES * HSTAGE_H * 2)

template <int EPI>
__global__ __launch_bounds__(256, 2) void hgemm(const __half* __restrict__ A,
                                                const __half* __restrict__ Bt,
                                                float* __restrict__ Cm,
                                                __half* __restrict__ qh,
                                                __half* __restrict__ kh,
                                                __half* __restrict__ vt,
                                                const float* __restrict__ tab,
                                                int N, int K) {
    extern __shared__ __half hsm[];
    const int tid = threadIdx.x;
    const int warp = tid >> 5, lane = tid & 31;
    const int wm = warp & 1, wn = warp >> 1;
    const int g = lane >> 2, t = lane & 3;
    const size_t m0 = (size_t)blockIdx.y * 128;
    const int n0 = blockIdx.x * 128;
    const int NT = K / HKT;

    const int l_row = tid >> 1;
    const int l_c = tid & 1;
    const __half* Ag = A + (m0 + l_row) * (size_t)K;
    const __half* Bg = Bt + (size_t)(n0 + l_row) * K;
    const uint32_t sb = (uint32_t)__cvta_generic_to_shared(hsm);

    const int a_off = (lane & 15) * HROW + (lane >> 4) * 8;
    const int b_off = (((lane >> 4) & 1) * 8 + (lane & 7)) * HROW + ((lane >> 3) & 1) * 8;

#define H_ISSUE(kt)                                                             \
    do {                                                                        \
        int s_ = (kt) & (HSTAGES - 1);                                          \
        uint32_t as_ = sb + (s_ * HSTAGE_H + l_row * HROW) * 2;                 \
        uint32_t bs_ = as_ + HA_H * 2;                                          \
        const __half* ag_ = Ag + (kt)*HKT;                                      \
        const __half* bg_ = Bg + (kt)*HKT;                                      \
        cp16(as_ + l_c * 16, ag_ + l_c * 8);                                    \
        cp16(as_ + (l_c + 2) * 16, ag_ + (l_c + 2) * 8);                        \
        cp16(bs_ + l_c * 16, bg_ + l_c * 8);                                    \
        cp16(bs_ + (l_c + 2) * 16, bg_ + (l_c + 2) * 8);                        \
    } while (0)

    H_ISSUE(0);
    asm volatile("cp.async.commit_group;\n");
    H_ISSUE(1);
    asm volatile("cp.async.commit_group;\n");
    H_ISSUE(2);
    asm volatile("cp.async.commit_group;\n");

    float acc[4][4][4];
#pragma unroll
    for (int i = 0; i < 4; i++)
#pragma unroll
        for (int j = 0; j < 4; j++)
#pragma unroll
            for (int r = 0; r < 4; r++) acc[i][j][r] = 0.f;

    for (int kt = 0; kt < NT; kt++) {
        asm volatile("cp.async.wait_group %0;\n" ::"n"(2));
        __syncthreads();

        if (kt + 3 < NT) H_ISSUE(kt + 3);
        asm volatile("cp.async.commit_group;\n");

        const uint32_t As = sb + ((kt & (HSTAGES - 1)) * HSTAGE_H) * 2;
        const uint32_t Bs = As + HA_H * 2;

#pragma unroll
        for (int s16 = 0; s16 < 32; s16 += 16) {
            uint32_t af[4][4], bf[4][2];
#pragma unroll
            for (int i = 0; i < 4; i++) {
                uint32_t addr = As + ((wm * 64 + i * 16) * HROW + s16 + a_off) * 2;
                LDSM_X4(af[i][0], af[i][1], af[i][2], af[i][3], addr);
            }
#pragma unroll
            for (int jp = 0; jp < 2; jp++) {
                uint32_t addr = Bs + ((wn * 32 + jp * 16) * HROW + s16 + b_off) * 2;
                LDSM_X4(bf[2 * jp][0], bf[2 * jp][1], bf[2 * jp + 1][0],
                        bf[2 * jp + 1][1], addr);
            }
#pragma unroll
            for (int i = 0; i < 4; i++)
#pragma unroll
                for (int j = 0; j < 4; j++) {
                    asm volatile(
                        "mma.sync.aligned.m16n8k16.row.col.f32.f16.f16.f32 "
                        "{%0,%1,%2,%3}, {%4,%5,%6,%7}, {%8,%9}, {%0,%1,%2,%3};"
                        : "+f"(acc[i][j][0]), "+f"(acc[i][j][1]),
                          "+f"(acc[i][j][2]), "+f"(acc[i][j][3])
                        : "r"(af[i][0]), "r"(af[i][1]), "r"(af[i][2]), "r"(af[i][3]),
                          "r"(bf[j][0]), "r"(bf[j][1]));
                }
        }
    }

    if (EPI == 0) {
#pragma unroll
        for (int i = 0; i < 4; i++)
#pragma unroll
            for (int j = 0; j < 4; j++) {
                size_t row = m0 + wm * 64 + i * 16 + g;
                int col = n0 + wn * 32 + j * 8 + 2 * t;
                *(float2*)(Cm + row * N + col) =
                    make_float2(acc[i][j][0], acc[i][j][1]);
                *(float2*)(Cm + (row + 8) * N + col) =
                    make_float2(acc[i][j][2], acc[i][j][3]);
            }
    } else {
        // Fused qkv epilogue. sec uniform per CTA (N-tiles don't straddle 1024s).
        const int sec = n0 >> 10;
#pragma unroll
        for (int i = 0; i < 4; i++) {
            const int mtok = (int)m0 + wm * 64 + i * 16 + g;  // and mtok+8
            const int b = mtok >> 11;
            const int t0 = mtok & (Tt - 1);                   // t1 = t0 + 8 (same b)
#pragma unroll
            for (int j = 0; j < 4; j++) {
                const int col = n0 + wn * 32 + j * 8 + 2 * t;
                const int h = (col >> 6) & 15;
                const int d = col & 63;                        // even
                const int bh = b * 16 + h;
                if (sec == 2) {
                    // v: transpose to [b,h,d,t]
                    __half* vb = vt + ((size_t)bh * 64 + d) * Tt + t0;
                    vb[0] = __float2half_rn(acc[i][j][0]);
                    vb[Tt] = __float2half_rn(acc[i][j][1]);
                    vb[8] = __float2half_rn(acc[i][j][2]);
                    vb[Tt + 8] = __float2half_rn(acc[i][j][3]);
                } else {
                    float2 cs0 = *(const float2*)(tab + t0 * 64 + d);
                    float2 cs1 = *(const float2*)(tab + (t0 + 8) * 64 + d);
                    float r00 = acc[i][j][0] * cs0.x - acc[i][j][1] * cs0.y;
                    float r01 = acc[i][j][1] * cs0.x + acc[i][j][0] * cs0.y;
                    float r10 = acc[i][j][2] * cs1.x - acc[i][j][3] * cs1.y;
                    float r11 = acc[i][j][3] * cs1.x + acc[i][j][2] * cs1.y;
                    size_t o0 = ((size_t)bh * Tt + t0) * 64 + d;
                    if (sec == 0) {
                        *(__half2*)(qh + o0) =
                            __floats2half2_rn(r00 * 0.125f, r01 * 0.125f);
                        *(__half2*)(qh + o0 + 8 * 64) =
                            __floats2half2_rn(r10 * 0.125f, r11 * 0.125f);
                    } else {
                        *(__half2*)(kh + o0) = __floats2half2_rn(r00, r01);
                        *(__half2*)(kh + o0 + 8 * 64) = __floats2half2_rn(r10, r11);
                    }
                }
            }
        }
    }
#undef H_ISSUE
}

// ---------------------------------------------------------------------------
// flash16 with ldmatrix (unchanged from R10; att16 out for GEMM2)
// ---------------------------------------------------------------------------
#define QS_H 72
#define FL_SMEM ((9216 + 2 * 9216) * 2)

__global__ __launch_bounds__(256, 2) void flash16(const __half* __restrict__ q16,
                                                  const __half* __restrict__ k16,
                                                  const __half* __restrict__ v16t,
                                                  __half* __restrict__ att) {
    extern __shared__ __half hs[];
    const int iq = gridDim.x - 1 - blockIdx.x;
    const int bh = blockIdx.y;
    const int b = bh >> 4, h = bh & 15;
    const int tid = threadIdx.x;
    const int w = tid >> 5, lane = tid & 31;
    const int g = lane >> 2, t = lane & 3;
    const int wr = w * 16;
    const size_t tbase = (size_t)bh * Tt;
    const uint32_t sb = (uint32_t)__cvta_generic_to_shared(hs);
    const int jmax = 2 * iq + 1;

    const int a_off = (lane & 15) * QS_H + (lane >> 4) * 8;
    const int b_off = (((lane >> 4) & 1) * 8 + (lane & 7)) * QS_H + ((lane >> 3) & 1) * 8;

#define ISSUE_KV(jt, s)                                                          \
    do {                                                                         \
        int row_ = tid >> 2;                                                     \
        int cb_ = tid & 3;                                                       \
        const __half* gk_ = k16 + (tbase + (jt)*64 + row_) * 64;                 \
        const __half* gv_ = v16t + ((size_t)bh * 64 + row_) * Tt + (jt)*64;      \
        uint32_t sk_ = sb + (9216 + (s)*9216 + row_ * QS_H) * 2;                 \
        uint32_t sv_ = sk_ + 4608 * 2;                                           \
        cp16(sk_ + cb_ * 16, gk_ + cb_ * 8);                                     \
        cp16(sk_ + (cb_ + 4) * 16, gk_ + (cb_ + 4) * 8);                         \
        cp16(sv_ + cb_ * 16, gv_ + cb_ * 8);                                     \
        cp16(sv_ + (cb_ + 4) * 16, gv_ + (cb_ + 4) * 8);                         \
    } while (0)

    {
        int row = tid >> 1;
        int cb = tid & 1;
        const __half* gq = q16 + (tbase + iq * 128 + row) * 64;
        uint32_t sq = sb + (row * QS_H) * 2;
#pragma unroll
        for (int c = cb; c < 8; c += 2) cp16(sq + c * 16, gq + c * 8);
    }
    ISSUE_KV(0, 0);
    asm volatile("cp.async.commit_group;\n");

    float oacc[8][4];
    float m0 = -1e30f, m1 = -1e30f, l0 = 0.f, l1 = 0.f;
#pragma unroll
    for (int ds = 0; ds < 8; ds++)
#pragma unroll
        for (int r = 0; r < 4; r++) oacc[ds][r] = 0.f;

    uint32_t qf[4][4];
    bool qf_loaded = false;

    for (int jt = 0; jt <= jmax; jt++) {
        if (jt + 1 <= jmax) ISSUE_KV(jt + 1, (jt + 1) & 1);
        asm volatile("cp.async.commit_group;\n");
        asm volatile("cp.async.wait_group %0;\n" ::"n"(1));
        __syncthreads();

        if (!qf_loaded) {
            qf_loaded = true;
#pragma unroll
            for (int kc = 0; kc < 4; kc++) {
                uint32_t addr = sb + (wr * QS_H + kc * 16 + a_off) * 2;
                LDSM_X4(qf[kc][0], qf[kc][1], qf[kc][2], qf[kc][3], addr);
            }
        }

        const uint32_t Ks = sb + (9216 + (jt & 1) * 9216) * 2;
        const uint32_t Vs = Ks + 4608 * 2;

        float sa[8][4];
#pragma unroll
        for (int ns = 0; ns < 8; ns++)
#pragma unroll
            for (int r = 0; r < 4; r++) sa[ns][r] = 0.f;

#pragma unroll
        for (int kc = 0; kc < 4; kc++)
#pragma unroll
            for (int ns2 = 0; ns2 < 4; ns2++) {
                uint32_t kb0, kb1, kb2, kb3;
                uint32_t addr = Ks + (ns2 * 16 * QS_H + kc * 16 + b_off) * 2;
                LDSM_X4(kb0, kb1, kb2, kb3, addr);
                asm volatile(
                    "mma.sync.aligned.m16n8k16.row.col.f32.f16.f16.f32 "
                    "{%0,%1,%2,%3}, {%4,%5,%6,%7}, {%8,%9}, {%0,%1,%2,%3};"
                    : "+f"(sa[2 * ns2][0]), "+f"(sa[2 * ns2][1]),
                      "+f"(sa[2 * ns2][2]), "+f"(sa[2 * ns2][3])
                    : "r"(qf[kc][0]), "r"(qf[kc][1]), "r"(qf[kc][2]), "r"(qf[kc][3]),
                      "r"(kb0), "r"(kb1));
                asm volatile(
                    "mma.sync.aligned.m16n8k16.row.col.f32.f16.f16.f32 "
                    "{%0,%1,%2,%3}, {%4,%5,%6,%7}, {%8,%9}, {%0,%1,%2,%3};"
                    : "+f"(sa[2 * ns2 + 1][0]), "+f"(sa[2 * ns2 + 1][1]),
                      "+f"(sa[2 * ns2 + 1][2]), "+f"(sa[2 * ns2 + 1][3])
                    : "r"(qf[kc][0]), "r"(qf[kc][1]), "r"(qf[kc][2]), "r"(qf[kc][3]),
                      "r"(kb2), "r"(kb3));
            }

        if (jt >= 2 * iq) {
            const int row0 = iq * 128 + wr + g;
            const int row1 = row0 + 8;
#pragma unroll
            for (int ns = 0; ns < 8; ns++) {
                int c0 = jt * 64 + ns * 8 + 2 * t;
                if (c0 > row0) sa[ns][0] = -1e30f;
                if (c0 + 1 > row0) sa[ns][1] = -1e30f;
                if (c0 > row1) sa[ns][2] = -1e30f;
                if (c0 + 1 > row1) sa[ns][3] = -1e30f;
            }
        }

        {
            float mx0 = -1e30f, mx1 = -1e30f;
#pragma unroll
            for (int ns = 0; ns < 8; ns++) {
                mx0 = fmaxf(mx0, fmaxf(sa[ns][0], sa[ns][1]));
                mx1 = fmaxf(mx1, fmaxf(sa[ns][2], sa[ns][3]));
            }
#pragma unroll
            for (int off = 1; off <= 2; off <<= 1) {
                mx0 = fmaxf(mx0, __shfl_xor_sync(0xffffffffu, mx0, off));
                mx1 = fmaxf(mx1, __shfl_xor_sync(0xffffffffu, mx1, off));
            }
            float mn0 = fmaxf(m0, mx0), mn1 = fmaxf(m1, mx1);
            float al0 = __expf(m0 - mn0), al1 = __expf(m1 - mn1);
            float s0 = 0.f, s1 = 0.f;
#pragma unroll
            for (int ns = 0; ns < 8; ns++) {
                sa[ns][0] = __expf(sa[ns][0] - mn0);
                sa[ns][1] = __expf(sa[ns][1] - mn0);
                sa[ns][2] = __expf(sa[ns][2] - mn1);
                sa[ns][3] = __expf(sa[ns][3] - mn1);
                s0 += sa[ns][0] + sa[ns][1];
                s1 += sa[ns][2] + sa[ns][3];
            }
#pragma unroll
            for (int off = 1; off <= 2; off <<= 1) {
                s0 += __shfl_xor_sync(0xffffffffu, s0, off);
                s1 += __shfl_xor_sync(0xffffffffu, s1, off);
            }
            l0 = l0 * al0 + s0;
            l1 = l1 * al1 + s1;
            m0 = mn0;
            m1 = mn1;
#pragma unroll
            for (int ds = 0; ds < 8; ds++) {
                oacc[ds][0] *= al0;
                oacc[ds][1] *= al0;
                oacc[ds][2] *= al1;
                oacc[ds][3] *= al1;
            }
        }

        uint32_t pf[4][4];
#pragma unroll
        for (int kc = 0; kc < 4; kc++) {
            __half2 h0 = __floats2half2_rn(sa[2 * kc][0], sa[2 * kc][1]);
            __half2 h1 = __floats2half2_rn(sa[2 * kc][2], sa[2 * kc][3]);
            __half2 h2 = __floats2half2_rn(sa[2 * kc + 1][0], sa[2 * kc + 1][1]);
            __half2 h3 = __floats2half2_rn(sa[2 * kc + 1][2], sa[2 * kc + 1][3]);
            pf[kc][0] = *(uint32_t*)&h0;
            pf[kc][1] = *(uint32_t*)&h1;
            pf[kc][2] = *(uint32_t*)&h2;
            pf[kc][3] = *(uint32_t*)&h3;
        }

#pragma unroll
        for (int kc = 0; kc < 4; kc++)
#pragma unroll
            for (int ds2 = 0; ds2 < 4; ds2++) {
                uint32_t vb0, vb1, vb2, vb3;
                uint32_t addr = Vs + (ds2 * 16 * QS_H + kc * 16 + b_off) * 2;
                LDSM_X4(vb0, vb1, vb2, vb3, addr);
                asm volatile(
                    "mma.sync.aligned.m16n8k16.row.col.f32.f16.f16.f32 "
                    "{%0,%1,%2,%3}, {%4,%5,%6,%7}, {%8,%9}, {%0,%1,%2,%3};"
                    : "+f"(oacc[2 * ds2][0]), "+f"(oacc[2 * ds2][1]),
                      "+f"(oacc[2 * ds2][2]), "+f"(oacc[2 * ds2][3])
                    : "r"(pf[kc][0]), "r"(pf[kc][1]), "r"(pf[kc][2]), "r"(pf[kc][3]),
                      "r"(vb0), "r"(vb1));
                asm volatile(
                    "mma.sync.aligned.m16n8k16.row.col.f32.f16.f16.f32 "
                    "{%0,%1,%2,%3}, {%4,%5,%6,%7}, {%8,%9}, {%0,%1,%2,%3};"
                    : "+f"(oacc[2 * ds2 + 1][0]), "+f"(oacc[2 * ds2 + 1][1]),
                      "+f"(oacc[2 * ds2 + 1][2]), "+f"(oacc[2 * ds2 + 1][3])
                    : "r"(pf[kc][0]), "r"(pf[kc][1]), "r"(pf[kc][2]), "r"(pf[kc][3]),
                      "r"(vb2), "r"(vb3));
            }

        __syncthreads();
    }

    const float il0 = 1.f / l0, il1 = 1.f / l1;
    __half* p0 = att + ((size_t)b * Tt + iq * 128 + wr + g) * Cc + h * 64;
    __half* p1 = p0 + 8 * (size_t)Cc;
#pragma unroll
    for (int ds = 0; ds < 8; ds++) {
        *(__half2*)(p0 + ds * 8 + 2 * t) =
            __floats2half2_rn(oacc[ds][0] * il0, oacc[ds][1] * il0);
        *(__half2*)(p1 + ds * 8 + 2 * t) =
            __floats2half2_rn(oacc[ds][2] * il1, oacc[ds][3] * il1);
    }
#undef ISSUE_KV
}

// ---------------------------------------------------------------------------
extern "C" void kernel_launch(void* const* d_in, const int* in_sizes, int n_in,
                              void* d_out, int out_size) {
    const float* x = (const float*)d_in[0];
    const float* Wqkv = (const float*)d_in[1];
    const float* Wout = (const float*)d_in[2];
    float* out = (float*)d_out;

    __half *x16, *wqkvT, *woutT, *qh, *kh, *vt, *att16;
    float* rope;
    cudaGetSymbolAddress((void**)&x16, g_x16);
    cudaGetSymbolAddress((void**)&wqkvT, g_wqkvT);
    cudaGetSymbolAddress((void**)&woutT, g_woutT);
    cudaGetSymbolAddress((void**)&qh, g_qh);
    cudaGetSymbolAddress((void**)&kh, g_kh);
    cudaGetSymbolAddress((void**)&vt, g_vt);
    cudaGetSymbolAddress((void**)&att16, g_att16);
    cudaGetSymbolAddress((void**)&rope, g_rope);

    cudaFuncSetAttribute(hgemm<0>, cudaFuncAttributeMaxDynamicSharedMemorySize,
                         HGEMM_SMEM);
    cudaFuncSetAttribute(hgemm<2>, cudaFuncAttributeMaxDynamicSharedMemorySize,
                         HGEMM_SMEM);
    cudaFuncSetAttribute(flash16, cudaFuncAttributeMaxDynamicSharedMemorySize,
                         FL_SMEM);

    f32_to_f16<<<(BTC / 4 + 255) / 256, 256>>>(x, x16, BTC / 4);
    transpose_to_half<<<dim3(3 * Cc / 32, Cc / 32), dim3(32, 8)>>>(Wqkv, wqkvT,
                                                                   Cc, 3 * Cc);
    transpose_to_half<<<dim3(Cc / 32, Cc / 32), dim3(32, 8)>>>(Wout, woutT, Cc, Cc);
    rope_table_k<<<Tt * 32 / 256, 256>>>(rope);

    // 1) fused: qkv = x16 @ WqkvT^T, RoPE in epilogue, scatter to qh/kh/vt
    hgemm<2><<<dim3(3072 / 128, 8192 / 128), 256, HGEMM_SMEM>>>(
        x16, wqkvT, nullptr, qh, kh, vt, rope, 3072, 1024);
    // 2) fp16 causal flash attention -> att16
    flash16<<<dim3(Tt / 128, Bb * Hh), 256, FL_SMEM>>>(qh, kh, vt, att16);
    // 3) out = att16 @ WoutT^T (fp32 out)
    hgemm<0><<<dim3(1024 / 128, 8192 / 128), 256, HGEMM_SMEM>>>(
        att16, woutT, out, nullptr, nullptr, nullptr, nullptr, 1024, 1024);
}